// round 2
// baseline (speedup 1.0000x reference)
#include <cuda_runtime.h>

typedef unsigned long long u64;

#define NN 512
#define C 128
#define NROWS (NN * NN)

// ---- scratch (device globals; no allocation allowed) ----
__device__ float g_a [(size_t)NROWS * C];
__device__ float g_b [(size_t)NROWS * C];
__device__ float g_go[(size_t)NROWS * C];
__device__ float g_k [(size_t)NROWS * C];

// ---- packed f32x2 helpers (Blackwell sm_103a) ----
__device__ __forceinline__ u64 pack2(float lo, float hi) {
    u64 r; asm("mov.b64 %0, {%1, %2};" : "=l"(r) : "f"(lo), "f"(hi)); return r;
}
__device__ __forceinline__ void unpack2(u64 v, float& lo, float& hi) {
    asm("mov.b64 {%0, %1}, %2;" : "=f"(lo), "=f"(hi) : "l"(v));
}
__device__ __forceinline__ u64 ffma2(u64 a, u64 b, u64 c) {
    u64 d; asm("fma.rn.f32x2 %0, %1, %2, %3;" : "=l"(d) : "l"(a), "l"(b), "l"(c)); return d;
}
__device__ __forceinline__ float sigm(float x) { return 1.0f / (1.0f + __expf(-x)); }

// Detect mask storage layout. Returns 1 if mask is int32 (bool widened by the
// harness), 0 if it is a raw byte array. For an int32 0/1 array, every byte at
// offset %4 != 0 is zero. For a random 0/1 byte array, P(first 64 bytes all
// look like int32) = 2^-48.
__device__ __forceinline__ int detect_mask_is_int32(const unsigned char* m) {
    const uint4* p = (const uint4*)m;
    unsigned acc = 0;
    #pragma unroll
    for (int i = 0; i < 4; i++) {
        uint4 v = p[i];
        acc |= v.x | v.y | v.z | v.w;
    }
    return (acc & 0xFFFFFF00u) == 0u;
}

__device__ __forceinline__ float mask_val(const unsigned char* m, int row, int is_i32) {
    int v = is_i32 ? ((const int*)m)[row] : (int)m[row];
    return v ? 0.0f : 1.0f;   // jnp.where(mask, 0, x)
}

// ============================================================================
// Kernel A: fused LayerNorm(z) + 5 linear projections + sigmoid gates + mask
//   writes a, b (masked, gated) and go = sigmoid(zn@Wgo+bgo)
//   16 rows per block, 256 threads. Each thread: 4 rows x 2 output columns.
// ============================================================================
__global__ __launch_bounds__(256)
void kA(const float* __restrict__ z, const unsigned char* __restrict__ mask,
        const float* __restrict__ gin, const float* __restrict__ bin,
        const float* __restrict__ Wa,  const float* __restrict__ ba,
        const float* __restrict__ Wga, const float* __restrict__ bga,
        const float* __restrict__ Wb,  const float* __restrict__ bb,
        const float* __restrict__ Wgb, const float* __restrict__ bgb,
        const float* __restrict__ Wgo, const float* __restrict__ bgo)
{
    __shared__ __align__(16) float zn[16 * C];
    __shared__ float msk[16];
    __shared__ int s_mi32;
    const int tid = threadIdx.x;
    const int rowbase = blockIdx.x * 16;

    if (tid == 0) s_mi32 = detect_mask_is_int32(mask);
    __syncthreads();
    const int mi32 = s_mi32;

    // ---- Phase 1: LayerNorm (each warp: 2 rows, 4 elems/lane) ----
    {
        const int w = tid >> 5, lane = tid & 31;
        #pragma unroll
        for (int rr = 0; rr < 2; rr++) {
            const int r = 2 * w + rr;
            const int row = rowbase + r;
            float4 x = *(const float4*)(z + (size_t)row * C + lane * 4);
            float s = x.x + x.y + x.z + x.w;
            float q = x.x * x.x + x.y * x.y + x.z * x.z + x.w * x.w;
            #pragma unroll
            for (int o = 16; o; o >>= 1) {
                s += __shfl_xor_sync(0xffffffffu, s, o);
                q += __shfl_xor_sync(0xffffffffu, q, o);
            }
            const float mean = s * (1.0f / C);
            const float var  = q * (1.0f / C) - mean * mean;
            const float rstd = rsqrtf(var + 1e-5f);
            float4 g4 = *(const float4*)(gin + lane * 4);
            float4 b4 = *(const float4*)(bin + lane * 4);
            float4 o4;
            o4.x = (x.x - mean) * rstd * g4.x + b4.x;
            o4.y = (x.y - mean) * rstd * g4.y + b4.y;
            o4.z = (x.z - mean) * rstd * g4.z + b4.z;
            o4.w = (x.w - mean) * rstd * g4.w + b4.w;
            *(float4*)(zn + r * C + lane * 4) = o4;
            if (lane == 0) msk[r] = mask_val(mask, row, mi32);
        }
    }
    __syncthreads();

    const int c2 = (tid & 63) * 2;   // this thread's output-column pair
    const int r0 = (tid >> 6) * 4;   // first of this thread's 4 rows
    const float* zr = zn + r0 * C;

    // ---- Phase 2a: a = mask * sigmoid(zn@Wga+bga) * (zn@Wa+ba) ----
    {
        u64 aa[4] = {0,0,0,0}, ag[4] = {0,0,0,0};
        #pragma unroll 4
        for (int k = 0; k < C; k++) {
            const u64 w1 = *(const u64*)(Wa  + k * C + c2);
            const u64 w2 = *(const u64*)(Wga + k * C + c2);
            #pragma unroll
            for (int r = 0; r < 4; r++) {
                const float zv = zr[r * C + k];
                const u64 z2 = pack2(zv, zv);
                aa[r] = ffma2(z2, w1, aa[r]);
                ag[r] = ffma2(z2, w2, ag[r]);
            }
        }
        const float b0 = ba[c2], b1 = ba[c2 + 1];
        const float g0 = bga[c2], g1 = bga[c2 + 1];
        #pragma unroll
        for (int r = 0; r < 4; r++) {
            float l0, l1, q0, q1;
            unpack2(aa[r], l0, l1); unpack2(ag[r], q0, q1);
            const float m = msk[r0 + r];
            float2 v;
            v.x = m * sigm(q0 + g0) * (l0 + b0);
            v.y = m * sigm(q1 + g1) * (l1 + b1);
            *(float2*)(g_a + (size_t)(rowbase + r0 + r) * C + c2) = v;
        }
    }

    // ---- Phase 2b: b = mask * sigmoid(zn@Wgb+bgb) * (zn@Wb+bb) ----
    {
        u64 aa[4] = {0,0,0,0}, ag[4] = {0,0,0,0};
        #pragma unroll 4
        for (int k = 0; k < C; k++) {
            const u64 w1 = *(const u64*)(Wb  + k * C + c2);
            const u64 w2 = *(const u64*)(Wgb + k * C + c2);
            #pragma unroll
            for (int r = 0; r < 4; r++) {
                const float zv = zr[r * C + k];
                const u64 z2 = pack2(zv, zv);
                aa[r] = ffma2(z2, w1, aa[r]);
                ag[r] = ffma2(z2, w2, ag[r]);
            }
        }
        const float b0 = bb[c2], b1 = bb[c2 + 1];
        const float g0 = bgb[c2], g1 = bgb[c2 + 1];
        #pragma unroll
        for (int r = 0; r < 4; r++) {
            float l0, l1, q0, q1;
            unpack2(aa[r], l0, l1); unpack2(ag[r], q0, q1);
            const float m = msk[r0 + r];
            float2 v;
            v.x = m * sigm(q0 + g0) * (l0 + b0);
            v.y = m * sigm(q1 + g1) * (l1 + b1);
            *(float2*)(g_b + (size_t)(rowbase + r0 + r) * C + c2) = v;
        }
    }

    // ---- Phase 2c: go = sigmoid(zn@Wgo + bgo) ----
    {
        u64 ao[4] = {0,0,0,0};
        #pragma unroll 4
        for (int k = 0; k < C; k++) {
            const u64 w1 = *(const u64*)(Wgo + k * C + c2);
            #pragma unroll
            for (int r = 0; r < 4; r++) {
                const float zv = zr[r * C + k];
                ao[r] = ffma2(pack2(zv, zv), w1, ao[r]);
            }
        }
        const float g0 = bgo[c2], g1 = bgo[c2 + 1];
        #pragma unroll
        for (int r = 0; r < 4; r++) {
            float l0, l1;
            unpack2(ao[r], l0, l1);
            float2 v;
            v.x = sigm(l0 + g0);
            v.y = sigm(l1 + g1);
            *(float2*)(g_go + (size_t)(rowbase + r0 + r) * C + c2) = v;
        }
    }
}

// ============================================================================
// Kernel B: k[i,j,c] = sum_k a[i,k,c] * b[j,k,c]
//   Block tile: 32 i x 32 j x 32 channels. 256 threads.
//   Thread: 8 i x 8 j x 2 channels (packed in f32x2) = 64 u64 accumulators.
//   Channel pairs map natively onto f32x2 lanes: no pack instructions needed.
// ============================================================================
__global__ __launch_bounds__(256)
void kB()
{
    __shared__ __align__(16) float as_[4 * 32 * 32];
    __shared__ __align__(16) float bs_[4 * 32 * 32];
    const int tid = threadIdx.x;
    const int i0 = blockIdx.x * 32, j0 = blockIdx.y * 32, c0 = blockIdx.z * 32;
    const int cc   = (tid & 15) * 2;     // channel pair within tile
    const int pos  = tid >> 4;           // 0..15
    const int isub = (pos & 3) * 8;
    const int jsub = (pos >> 2) * 8;

    u64 acc[8][8];
    #pragma unroll
    for (int ii = 0; ii < 8; ii++)
        #pragma unroll
        for (int jj = 0; jj < 8; jj++) acc[ii][jj] = 0ULL;

    for (int k0 = 0; k0 < NN; k0 += 4) {
        __syncthreads();
        #pragma unroll
        for (int m = 0; m < 4; m++) {
            const int lin = tid + 256 * m;       // 0..1023
            const int i   = lin >> 5;            // 0..31 (tile row)
            const int kk  = (lin >> 3) & 3;      // 0..3
            const int c4  = (lin & 7) * 4;       // 0..28
            const size_t ga = ((size_t)(i0 + i) * NN + (k0 + kk)) * C + c0 + c4;
            const size_t gb = ((size_t)(j0 + i) * NN + (k0 + kk)) * C + c0 + c4;
            *(float4*)(as_ + kk * 1024 + i * 32 + c4) = *(const float4*)(g_a + ga);
            *(float4*)(bs_ + kk * 1024 + i * 32 + c4) = *(const float4*)(g_b + gb);
        }
        __syncthreads();
        #pragma unroll
        for (int kk = 0; kk < 4; kk++) {
            u64 av[8], bv[8];
            #pragma unroll
            for (int ii = 0; ii < 8; ii++)
                av[ii] = *(const u64*)(as_ + kk * 1024 + (isub + ii) * 32 + cc);
            #pragma unroll
            for (int jj = 0; jj < 8; jj++)
                bv[jj] = *(const u64*)(bs_ + kk * 1024 + (jsub + jj) * 32 + cc);
            #pragma unroll
            for (int ii = 0; ii < 8; ii++)
                #pragma unroll
                for (int jj = 0; jj < 8; jj++)
                    acc[ii][jj] = ffma2(av[ii], bv[jj], acc[ii][jj]);
        }
    }

    #pragma unroll
    for (int ii = 0; ii < 8; ii++)
        #pragma unroll
        for (int jj = 0; jj < 8; jj++)
            *(u64*)(g_k + ((size_t)(i0 + isub + ii) * NN + (j0 + jsub + jj)) * C + c0 + cc)
                = acc[ii][jj];
}

// ============================================================================
// Kernel C: out = go * (LayerNorm(k) @ Wo + bo)
//   Same structure as kernel A, single projection.
// ============================================================================
__global__ __launch_bounds__(256)
void kC(const float* __restrict__ go_, const float* __restrict__ bo_,
        const float* __restrict__ Wo,  const float* __restrict__ bo,
        float* __restrict__ out)
{
    __shared__ __align__(16) float kn[16 * C];
    const int tid = threadIdx.x;
    const int rowbase = blockIdx.x * 16;

    {
        const int w = tid >> 5, lane = tid & 31;
        #pragma unroll
        for (int rr = 0; rr < 2; rr++) {
            const int r = 2 * w + rr;
            const int row = rowbase + r;
            float4 x = *(const float4*)(g_k + (size_t)row * C + lane * 4);
            float s = x.x + x.y + x.z + x.w;
            float q = x.x * x.x + x.y * x.y + x.z * x.z + x.w * x.w;
            #pragma unroll
            for (int o = 16; o; o >>= 1) {
                s += __shfl_xor_sync(0xffffffffu, s, o);
                q += __shfl_xor_sync(0xffffffffu, q, o);
            }
            const float mean = s * (1.0f / C);
            const float var  = q * (1.0f / C) - mean * mean;
            const float rstd = rsqrtf(var + 1e-5f);
            float4 g4 = *(const float4*)(go_ + lane * 4);
            float4 b4 = *(const float4*)(bo_ + lane * 4);
            float4 o4;
            o4.x = (x.x - mean) * rstd * g4.x + b4.x;
            o4.y = (x.y - mean) * rstd * g4.y + b4.y;
            o4.z = (x.z - mean) * rstd * g4.z + b4.z;
            o4.w = (x.w - mean) * rstd * g4.w + b4.w;
            *(float4*)(kn + r * C + lane * 4) = o4;
        }
    }
    __syncthreads();

    const int c2 = (tid & 63) * 2;
    const int r0 = (tid >> 6) * 4;
    const float* kr = kn + r0 * C;

    u64 ao[4] = {0,0,0,0};
    #pragma unroll 4
    for (int k = 0; k < C; k++) {
        const u64 w1 = *(const u64*)(Wo + k * C + c2);
        #pragma unroll
        for (int r = 0; r < 4; r++) {
            const float zv = kr[r * C + k];
            ao[r] = ffma2(pack2(zv, zv), w1, ao[r]);
        }
    }
    const float b0 = bo[c2], b1 = bo[c2 + 1];
    #pragma unroll
    for (int r = 0; r < 4; r++) {
        float l0, l1;
        unpack2(ao[r], l0, l1);
        const size_t row = rowbase + r0 + r;
        const float2 gg = *(const float2*)(g_go + row * C + c2);
        float2 v;
        v.x = gg.x * (l0 + b0);
        v.y = gg.y * (l1 + b1);
        *(float2*)(out + row * C + c2) = v;
    }
}

// ============================================================================
extern "C" void kernel_launch(void* const* d_in, const int* in_sizes, int n_in,
                              void* d_out, int out_size)
{
    const float*         z    = (const float*)d_in[0];
    const unsigned char* mask = (const unsigned char*)d_in[1];
    const float* gin  = (const float*)d_in[2];
    const float* bin  = (const float*)d_in[3];
    const float* Wa   = (const float*)d_in[4];
    const float* ba   = (const float*)d_in[5];
    const float* Wga  = (const float*)d_in[6];
    const float* bga  = (const float*)d_in[7];
    const float* Wb   = (const float*)d_in[8];
    const float* bb   = (const float*)d_in[9];
    const float* Wgb  = (const float*)d_in[10];
    const float* bgb  = (const float*)d_in[11];
    const float* g_o  = (const float*)d_in[12];
    const float* b_o  = (const float*)d_in[13];
    const float* Wgo  = (const float*)d_in[14];
    const float* bgo  = (const float*)d_in[15];
    const float* Wo   = (const float*)d_in[16];
    const float* bo   = (const float*)d_in[17];
    float* out = (float*)d_out;

    kA<<<NROWS / 16, 256>>>(z, mask, gin, bin, Wa, ba, Wga, bga,
                            Wb, bb, Wgb, bgb, Wgo, bgo);
    dim3 gridB(NN / 32, NN / 32, C / 32);
    kB<<<gridB, 256>>>();
    kC<<<NROWS / 16, 256>>>(g_o, b_o, Wo, bo, out);
}

// round 3
// speedup vs baseline: 1.0001x; 1.0001x over previous
#include <cuda_runtime.h>

typedef unsigned long long u64;

#define NN 512
#define C 128
#define NROWS (NN * NN)

// ---- scratch (device globals; no allocation allowed) ----
__device__ float g_a [(size_t)NROWS * C];
__device__ float g_b [(size_t)NROWS * C];
__device__ float g_go[(size_t)NROWS * C];
__device__ float g_k [(size_t)NROWS * C];

// ---- packed f32x2 helpers (Blackwell sm_103a) ----
__device__ __forceinline__ u64 pack2(float lo, float hi) {
    u64 r; asm("mov.b64 %0, {%1, %2};" : "=l"(r) : "f"(lo), "f"(hi)); return r;
}
__device__ __forceinline__ void unpack2(u64 v, float& lo, float& hi) {
    asm("mov.b64 {%0, %1}, %2;" : "=f"(lo), "=f"(hi) : "l"(v));
}
__device__ __forceinline__ u64 ffma2(u64 a, u64 b, u64 c) {
    u64 d; asm("fma.rn.f32x2 %0, %1, %2, %3;" : "=l"(d) : "l"(a), "l"(b), "l"(c)); return d;
}
__device__ __forceinline__ float sigm(float x) { return 1.0f / (1.0f + __expf(-x)); }

// Detect mask storage layout. Returns 1 if mask is int32 (bool widened by the
// harness), 0 if it is a raw byte array. For an int32 0/1 array, every byte at
// offset %4 != 0 is zero. For a random 0/1 byte array, P(first 64 bytes all
// look like int32) = 2^-48.
__device__ __forceinline__ int detect_mask_is_int32(const unsigned char* m) {
    const uint4* p = (const uint4*)m;
    unsigned acc = 0;
    #pragma unroll
    for (int i = 0; i < 4; i++) {
        uint4 v = p[i];
        acc |= v.x | v.y | v.z | v.w;
    }
    return (acc & 0xFFFFFF00u) == 0u;
}

__device__ __forceinline__ float mask_val(const unsigned char* m, int row, int is_i32) {
    int v = is_i32 ? ((const int*)m)[row] : (int)m[row];
    return v ? 0.0f : 1.0f;   // jnp.where(mask, 0, x)
}

// ============================================================================
// Kernel A: fused LayerNorm(z) + 5 linear projections + sigmoid gates + mask
//   writes a, b (masked, gated) and go = sigmoid(zn@Wgo+bgo)
//   16 rows per block, 256 threads. Each thread: 4 rows x 2 output columns.
// ============================================================================
__global__ __launch_bounds__(256)
void kA(const float* __restrict__ z, const unsigned char* __restrict__ mask,
        const float* __restrict__ gin, const float* __restrict__ bin,
        const float* __restrict__ Wa,  const float* __restrict__ ba,
        const float* __restrict__ Wga, const float* __restrict__ bga,
        const float* __restrict__ Wb,  const float* __restrict__ bb,
        const float* __restrict__ Wgb, const float* __restrict__ bgb,
        const float* __restrict__ Wgo, const float* __restrict__ bgo)
{
    __shared__ __align__(16) float zn[16 * C];
    __shared__ float msk[16];
    __shared__ int s_mi32;
    const int tid = threadIdx.x;
    const int rowbase = blockIdx.x * 16;

    if (tid == 0) s_mi32 = detect_mask_is_int32(mask);
    __syncthreads();
    const int mi32 = s_mi32;

    // ---- Phase 1: LayerNorm (each warp: 2 rows, 4 elems/lane) ----
    {
        const int w = tid >> 5, lane = tid & 31;
        #pragma unroll
        for (int rr = 0; rr < 2; rr++) {
            const int r = 2 * w + rr;
            const int row = rowbase + r;
            float4 x = *(const float4*)(z + (size_t)row * C + lane * 4);
            float s = x.x + x.y + x.z + x.w;
            float q = x.x * x.x + x.y * x.y + x.z * x.z + x.w * x.w;
            #pragma unroll
            for (int o = 16; o; o >>= 1) {
                s += __shfl_xor_sync(0xffffffffu, s, o);
                q += __shfl_xor_sync(0xffffffffu, q, o);
            }
            const float mean = s * (1.0f / C);
            const float var  = q * (1.0f / C) - mean * mean;
            const float rstd = rsqrtf(var + 1e-5f);
            float4 g4 = *(const float4*)(gin + lane * 4);
            float4 b4 = *(const float4*)(bin + lane * 4);
            float4 o4;
            o4.x = (x.x - mean) * rstd * g4.x + b4.x;
            o4.y = (x.y - mean) * rstd * g4.y + b4.y;
            o4.z = (x.z - mean) * rstd * g4.z + b4.z;
            o4.w = (x.w - mean) * rstd * g4.w + b4.w;
            *(float4*)(zn + r * C + lane * 4) = o4;
            if (lane == 0) msk[r] = mask_val(mask, row, mi32);
        }
    }
    __syncthreads();

    const int c2 = (tid & 63) * 2;   // this thread's output-column pair
    const int r0 = (tid >> 6) * 4;   // first of this thread's 4 rows
    const float* zr = zn + r0 * C;

    // ---- Phase 2a: a = mask * sigmoid(zn@Wga+bga) * (zn@Wa+ba) ----
    {
        u64 aa[4] = {0,0,0,0}, ag[4] = {0,0,0,0};
        #pragma unroll 4
        for (int k = 0; k < C; k++) {
            const u64 w1 = *(const u64*)(Wa  + k * C + c2);
            const u64 w2 = *(const u64*)(Wga + k * C + c2);
            #pragma unroll
            for (int r = 0; r < 4; r++) {
                const float zv = zr[r * C + k];
                const u64 z2 = pack2(zv, zv);
                aa[r] = ffma2(z2, w1, aa[r]);
                ag[r] = ffma2(z2, w2, ag[r]);
            }
        }
        const float b0 = ba[c2], b1 = ba[c2 + 1];
        const float g0 = bga[c2], g1 = bga[c2 + 1];
        #pragma unroll
        for (int r = 0; r < 4; r++) {
            float l0, l1, q0, q1;
            unpack2(aa[r], l0, l1); unpack2(ag[r], q0, q1);
            const float m = msk[r0 + r];
            float2 v;
            v.x = m * sigm(q0 + g0) * (l0 + b0);
            v.y = m * sigm(q1 + g1) * (l1 + b1);
            *(float2*)(g_a + (size_t)(rowbase + r0 + r) * C + c2) = v;
        }
    }

    // ---- Phase 2b: b = mask * sigmoid(zn@Wgb+bgb) * (zn@Wb+bb) ----
    {
        u64 aa[4] = {0,0,0,0}, ag[4] = {0,0,0,0};
        #pragma unroll 4
        for (int k = 0; k < C; k++) {
            const u64 w1 = *(const u64*)(Wb  + k * C + c2);
            const u64 w2 = *(const u64*)(Wgb + k * C + c2);
            #pragma unroll
            for (int r = 0; r < 4; r++) {
                const float zv = zr[r * C + k];
                const u64 z2 = pack2(zv, zv);
                aa[r] = ffma2(z2, w1, aa[r]);
                ag[r] = ffma2(z2, w2, ag[r]);
            }
        }
        const float b0 = bb[c2], b1 = bb[c2 + 1];
        const float g0 = bgb[c2], g1 = bgb[c2 + 1];
        #pragma unroll
        for (int r = 0; r < 4; r++) {
            float l0, l1, q0, q1;
            unpack2(aa[r], l0, l1); unpack2(ag[r], q0, q1);
            const float m = msk[r0 + r];
            float2 v;
            v.x = m * sigm(q0 + g0) * (l0 + b0);
            v.y = m * sigm(q1 + g1) * (l1 + b1);
            *(float2*)(g_b + (size_t)(rowbase + r0 + r) * C + c2) = v;
        }
    }

    // ---- Phase 2c: go = sigmoid(zn@Wgo + bgo) ----
    {
        u64 ao[4] = {0,0,0,0};
        #pragma unroll 4
        for (int k = 0; k < C; k++) {
            const u64 w1 = *(const u64*)(Wgo + k * C + c2);
            #pragma unroll
            for (int r = 0; r < 4; r++) {
                const float zv = zr[r * C + k];
                ao[r] = ffma2(pack2(zv, zv), w1, ao[r]);
            }
        }
        const float g0 = bgo[c2], g1 = bgo[c2 + 1];
        #pragma unroll
        for (int r = 0; r < 4; r++) {
            float l0, l1;
            unpack2(ao[r], l0, l1);
            float2 v;
            v.x = sigm(l0 + g0);
            v.y = sigm(l1 + g1);
            *(float2*)(g_go + (size_t)(rowbase + r0 + r) * C + c2) = v;
        }
    }
}

// ============================================================================
// Kernel B: k[i,j,c] = sum_k a[i,k,c] * b[j,k,c]
//   Block tile: 32 i x 32 j x 32 channels. 256 threads.
//   Thread: 8 i x 8 j x 2 channels (packed in f32x2) = 64 u64 accumulators.
//   Channel pairs map natively onto f32x2 lanes: no pack instructions needed.
// ============================================================================
__global__ __launch_bounds__(256)
void kB()
{
    __shared__ __align__(16) float as_[4 * 32 * 32];
    __shared__ __align__(16) float bs_[4 * 32 * 32];
    const int tid = threadIdx.x;
    const int i0 = blockIdx.x * 32, j0 = blockIdx.y * 32, c0 = blockIdx.z * 32;
    const int cc   = (tid & 15) * 2;     // channel pair within tile
    const int pos  = tid >> 4;           // 0..15
    const int isub = (pos & 3) * 8;
    const int jsub = (pos >> 2) * 8;

    u64 acc[8][8];
    #pragma unroll
    for (int ii = 0; ii < 8; ii++)
        #pragma unroll
        for (int jj = 0; jj < 8; jj++) acc[ii][jj] = 0ULL;

    for (int k0 = 0; k0 < NN; k0 += 4) {
        __syncthreads();
        #pragma unroll
        for (int m = 0; m < 4; m++) {
            const int lin = tid + 256 * m;       // 0..1023
            const int i   = lin >> 5;            // 0..31 (tile row)
            const int kk  = (lin >> 3) & 3;      // 0..3
            const int c4  = (lin & 7) * 4;       // 0..28
            const size_t ga = ((size_t)(i0 + i) * NN + (k0 + kk)) * C + c0 + c4;
            const size_t gb = ((size_t)(j0 + i) * NN + (k0 + kk)) * C + c0 + c4;
            *(float4*)(as_ + kk * 1024 + i * 32 + c4) = *(const float4*)(g_a + ga);
            *(float4*)(bs_ + kk * 1024 + i * 32 + c4) = *(const float4*)(g_b + gb);
        }
        __syncthreads();
        #pragma unroll
        for (int kk = 0; kk < 4; kk++) {
            u64 av[8], bv[8];
            #pragma unroll
            for (int ii = 0; ii < 8; ii++)
                av[ii] = *(const u64*)(as_ + kk * 1024 + (isub + ii) * 32 + cc);
            #pragma unroll
            for (int jj = 0; jj < 8; jj++)
                bv[jj] = *(const u64*)(bs_ + kk * 1024 + (jsub + jj) * 32 + cc);
            #pragma unroll
            for (int ii = 0; ii < 8; ii++)
                #pragma unroll
                for (int jj = 0; jj < 8; jj++)
                    acc[ii][jj] = ffma2(av[ii], bv[jj], acc[ii][jj]);
        }
    }

    #pragma unroll
    for (int ii = 0; ii < 8; ii++)
        #pragma unroll
        for (int jj = 0; jj < 8; jj++)
            *(u64*)(g_k + ((size_t)(i0 + isub + ii) * NN + (j0 + jsub + jj)) * C + c0 + cc)
                = acc[ii][jj];
}

// ============================================================================
// Kernel C: out = go * (LayerNorm(k) @ Wo + bo)
//   Same structure as kernel A, single projection.
// ============================================================================
__global__ __launch_bounds__(256)
void kC(const float* __restrict__ go_, const float* __restrict__ bo_,
        const float* __restrict__ Wo,  const float* __restrict__ bo,
        float* __restrict__ out)
{
    __shared__ __align__(16) float kn[16 * C];
    const int tid = threadIdx.x;
    const int rowbase = blockIdx.x * 16;

    {
        const int w = tid >> 5, lane = tid & 31;
        #pragma unroll
        for (int rr = 0; rr < 2; rr++) {
            const int r = 2 * w + rr;
            const int row = rowbase + r;
            float4 x = *(const float4*)(g_k + (size_t)row * C + lane * 4);
            float s = x.x + x.y + x.z + x.w;
            float q = x.x * x.x + x.y * x.y + x.z * x.z + x.w * x.w;
            #pragma unroll
            for (int o = 16; o; o >>= 1) {
                s += __shfl_xor_sync(0xffffffffu, s, o);
                q += __shfl_xor_sync(0xffffffffu, q, o);
            }
            const float mean = s * (1.0f / C);
            const float var  = q * (1.0f / C) - mean * mean;
            const float rstd = rsqrtf(var + 1e-5f);
            float4 g4 = *(const float4*)(go_ + lane * 4);
            float4 b4 = *(const float4*)(bo_ + lane * 4);
            float4 o4;
            o4.x = (x.x - mean) * rstd * g4.x + b4.x;
            o4.y = (x.y - mean) * rstd * g4.y + b4.y;
            o4.z = (x.z - mean) * rstd * g4.z + b4.z;
            o4.w = (x.w - mean) * rstd * g4.w + b4.w;
            *(float4*)(kn + r * C + lane * 4) = o4;
        }
    }
    __syncthreads();

    const int c2 = (tid & 63) * 2;
    const int r0 = (tid >> 6) * 4;
    const float* kr = kn + r0 * C;

    u64 ao[4] = {0,0,0,0};
    #pragma unroll 4
    for (int k = 0; k < C; k++) {
        const u64 w1 = *(const u64*)(Wo + k * C + c2);
        #pragma unroll
        for (int r = 0; r < 4; r++) {
            const float zv = kr[r * C + k];
            ao[r] = ffma2(pack2(zv, zv), w1, ao[r]);
        }
    }
    const float b0 = bo[c2], b1 = bo[c2 + 1];
    #pragma unroll
    for (int r = 0; r < 4; r++) {
        float l0, l1;
        unpack2(ao[r], l0, l1);
        const size_t row = rowbase + r0 + r;
        const float2 gg = *(const float2*)(g_go + row * C + c2);
        float2 v;
        v.x = gg.x * (l0 + b0);
        v.y = gg.y * (l1 + b1);
        *(float2*)(out + row * C + c2) = v;
    }
}

// ============================================================================
extern "C" void kernel_launch(void* const* d_in, const int* in_sizes, int n_in,
                              void* d_out, int out_size)
{
    const float*         z    = (const float*)d_in[0];
    const unsigned char* mask = (const unsigned char*)d_in[1];
    const float* gin  = (const float*)d_in[2];
    const float* bin  = (const float*)d_in[3];
    const float* Wa   = (const float*)d_in[4];
    const float* ba   = (const float*)d_in[5];
    const float* Wga  = (const float*)d_in[6];
    const float* bga  = (const float*)d_in[7];
    const float* Wb   = (const float*)d_in[8];
    const float* bb   = (const float*)d_in[9];
    const float* Wgb  = (const float*)d_in[10];
    const float* bgb  = (const float*)d_in[11];
    const float* g_o  = (const float*)d_in[12];
    const float* b_o  = (const float*)d_in[13];
    const float* Wgo  = (const float*)d_in[14];
    const float* bgo  = (const float*)d_in[15];
    const float* Wo   = (const float*)d_in[16];
    const float* bo   = (const float*)d_in[17];
    float* out = (float*)d_out;

    kA<<<NROWS / 16, 256>>>(z, mask, gin, bin, Wa, ba, Wga, bga,
                            Wb, bb, Wgb, bgb, Wgo, bgo);
    dim3 gridB(NN / 32, NN / 32, C / 32);
    kB<<<gridB, 256>>>();
    kC<<<NROWS / 16, 256>>>(g_o, b_o, Wo, bo, out);
}

// round 5
// speedup vs baseline: 1.2790x; 1.2788x over previous
#include <cuda_runtime.h>

typedef unsigned long long u64;
typedef unsigned int u32;

#define NN 512
#define C 128
#define NROWS (NN * NN)
#define PLANE ((size_t)NROWS)

// ---- scratch planes: [c][flat_row] fp32 ----
__device__ float g_af[(size_t)C * NROWS];
__device__ float g_bf[(size_t)C * NROWS];
__device__ float g_go[(size_t)NROWS * C];   // [row][c]
__device__ float g_kf[(size_t)C * NROWS];   // [c][i*512+j]

// ---- helpers ----
__device__ __forceinline__ u64 pack2(float lo, float hi) {
    u64 r; asm("mov.b64 %0, {%1, %2};" : "=l"(r) : "f"(lo), "f"(hi)); return r;
}
__device__ __forceinline__ void unpack2(u64 v, float& lo, float& hi) {
    asm("mov.b64 {%0, %1}, %2;" : "=f"(lo), "=f"(hi) : "l"(v));
}
__device__ __forceinline__ u64 ffma2(u64 a, u64 b, u64 c) {
    u64 d; asm("fma.rn.f32x2 %0, %1, %2, %3;" : "=l"(d) : "l"(a), "l"(b), "l"(c)); return d;
}
__device__ __forceinline__ float sigm(float x) { return 1.0f / (1.0f + __expf(-x)); }
__device__ __forceinline__ u32 bf16x2(float hi_val, float lo_val) {  // {upper=hi_val, lower=lo_val}
    u32 r; asm("cvt.rn.bf16x2.f32 %0, %1, %2;" : "=r"(r) : "f"(hi_val), "f"(lo_val)); return r;
}
__device__ __forceinline__ u32 smem_u32(const void* p) {
    u32 a; asm("{ .reg .u64 t; cvta.to.shared.u64 t, %1; cvt.u32.u64 %0, t; }" : "=r"(a) : "l"(p));
    return a;
}
__device__ __forceinline__ u32 sw128(u32 x) { return x ^ ((x >> 3) & 0x70); }

__device__ __forceinline__ void ldsm4(u32 addr, u32* r) {
    asm volatile("ldmatrix.sync.aligned.m8n8.x4.shared.b16 {%0,%1,%2,%3}, [%4];"
        : "=r"(r[0]), "=r"(r[1]), "=r"(r[2]), "=r"(r[3]) : "r"(addr));
}
__device__ __forceinline__ void mma_bf16(float* c, const u32* a, const u32* b) {
    asm volatile("mma.sync.aligned.m16n8k16.row.col.f32.bf16.bf16.f32 "
        "{%0,%1,%2,%3}, {%4,%5,%6,%7}, {%8,%9}, {%0,%1,%2,%3};"
        : "+f"(c[0]), "+f"(c[1]), "+f"(c[2]), "+f"(c[3])
        : "r"(a[0]), "r"(a[1]), "r"(a[2]), "r"(a[3]), "r"(b[0]), "r"(b[1]));
}

__device__ __forceinline__ int detect_mask_is_int32(const unsigned char* m) {
    const uint4* p = (const uint4*)m;
    unsigned acc = 0;
    #pragma unroll
    for (int i = 0; i < 4; i++) { uint4 v = p[i]; acc |= v.x | v.y | v.z | v.w; }
    return (acc & 0xFFFFFF00u) == 0u;
}
__device__ __forceinline__ float mask_val(const unsigned char* m, int row, int i32) {
    int v = i32 ? ((const int*)m)[row] : (int)m[row];
    return v ? 0.0f : 1.0f;
}

// ============================================================================
// Kernel A: LN(z) + 5 gated projections. 32 rows/block, 256 threads.
// Emits fp32 planes g_af/g_bf ([c][row]) and g_go ([row][c]).
// ============================================================================
#define ZST 130
__global__ __launch_bounds__(256)
void kA(const float* __restrict__ z, const unsigned char* __restrict__ mask,
        const float* __restrict__ gin, const float* __restrict__ bin,
        const float* __restrict__ Wa,  const float* __restrict__ ba,
        const float* __restrict__ Wga, const float* __restrict__ bga,
        const float* __restrict__ Wb,  const float* __restrict__ bb,
        const float* __restrict__ Wgb, const float* __restrict__ bgb,
        const float* __restrict__ Wgo, const float* __restrict__ bgo)
{
    __shared__ __align__(16) u64 znd[32 * ZST];
    __shared__ float msk[32];
    __shared__ int s_mi32;
    const int tid = threadIdx.x;
    const int rowbase = blockIdx.x * 32;

    if (tid == 0) s_mi32 = detect_mask_is_int32(mask);

    { // LN: warp w -> rows 4w..4w+3
        const int w = tid >> 5, lane = tid & 31;
        #pragma unroll
        for (int rr = 0; rr < 4; rr++) {
            const int r = 4 * w + rr, row = rowbase + r;
            float4 x = *(const float4*)(z + (size_t)row * C + lane * 4);
            float s = x.x + x.y + x.z + x.w;
            float q = x.x*x.x + x.y*x.y + x.z*x.z + x.w*x.w;
            #pragma unroll
            for (int o = 16; o; o >>= 1) {
                s += __shfl_xor_sync(~0u, s, o);
                q += __shfl_xor_sync(~0u, q, o);
            }
            const float mean = s * (1.0f / C);
            const float rstd = rsqrtf(q * (1.0f / C) - mean * mean + 1e-5f);
            float4 g4 = *(const float4*)(gin + lane * 4);
            float4 b4 = *(const float4*)(bin + lane * 4);
            float v0 = (x.x - mean) * rstd * g4.x + b4.x;
            float v1 = (x.y - mean) * rstd * g4.y + b4.y;
            float v2 = (x.z - mean) * rstd * g4.z + b4.z;
            float v3 = (x.w - mean) * rstd * g4.w + b4.w;
            u64* d = znd + r * ZST + lane * 4;
            d[0] = pack2(v0, v0); d[1] = pack2(v1, v1);
            d[2] = pack2(v2, v2); d[3] = pack2(v3, v3);
        }
    }
    __syncthreads();
    if (tid < 32) msk[tid] = mask_val(mask, rowbase + tid, s_mi32);
    __syncthreads();

    const int c2 = (tid & 63) * 2;
    const int r0 = (tid >> 6) * 8;
    const u64* zr = znd + r0 * ZST;

    // ---- dual-gemm + gate + mask -> plane (for a, then b) ----
    #pragma unroll 1
    for (int t = 0; t < 2; t++) {
        const float* W1 = t ? Wb  : Wa;
        const float* W2 = t ? Wgb : Wga;
        const float* B1 = t ? bb  : ba;
        const float* B2 = t ? bgb : bga;
        float* plane = t ? g_bf : g_af;
        u64 aa[8], ag[8];
        #pragma unroll
        for (int r = 0; r < 8; r++) { aa[r] = 0; ag[r] = 0; }
        #pragma unroll 2
        for (int k = 0; k < C; k += 2) {
            const u64 w1a = *(const u64*)(W1 + k * C + c2);
            const u64 w1b = *(const u64*)(W1 + (k + 1) * C + c2);
            const u64 w2a = *(const u64*)(W2 + k * C + c2);
            const u64 w2b = *(const u64*)(W2 + (k + 1) * C + c2);
            #pragma unroll
            for (int r = 0; r < 8; r++) {
                const ulonglong2 zz = *(const ulonglong2*)(zr + r * ZST + k);
                aa[r] = ffma2(zz.x, w1a, aa[r]); aa[r] = ffma2(zz.y, w1b, aa[r]);
                ag[r] = ffma2(zz.x, w2a, ag[r]); ag[r] = ffma2(zz.y, w2b, ag[r]);
            }
        }
        const float2 b1 = *(const float2*)(B1 + c2);
        const float2 b2 = *(const float2*)(B2 + c2);
        float v0[8], v1[8];
        #pragma unroll
        for (int r = 0; r < 8; r++) {
            float l0, l1, q0, q1;
            unpack2(aa[r], l0, l1); unpack2(ag[r], q0, q1);
            const float m = msk[r0 + r];
            v0[r] = m * sigm(q0 + b2.x) * (l0 + b1.x);
            v1[r] = m * sigm(q1 + b2.y) * (l1 + b1.y);
        }
        float* p0 = plane + (size_t)c2 * PLANE + rowbase + r0;
        float* p1 = plane + (size_t)(c2 + 1) * PLANE + rowbase + r0;
        *(float4*)p0       = make_float4(v0[0], v0[1], v0[2], v0[3]);
        *(float4*)(p0 + 4) = make_float4(v0[4], v0[5], v0[6], v0[7]);
        *(float4*)p1       = make_float4(v1[0], v1[1], v1[2], v1[3]);
        *(float4*)(p1 + 4) = make_float4(v1[4], v1[5], v1[6], v1[7]);
    }

    // ---- go = sigmoid(zn@Wgo + bgo), row-major ----
    {
        u64 ao[8];
        #pragma unroll
        for (int r = 0; r < 8; r++) ao[r] = 0;
        #pragma unroll 2
        for (int k = 0; k < C; k += 2) {
            const u64 wa = *(const u64*)(Wgo + k * C + c2);
            const u64 wb = *(const u64*)(Wgo + (k + 1) * C + c2);
            #pragma unroll
            for (int r = 0; r < 8; r++) {
                const ulonglong2 zz = *(const ulonglong2*)(zr + r * ZST + k);
                ao[r] = ffma2(zz.x, wa, ao[r]); ao[r] = ffma2(zz.y, wb, ao[r]);
            }
        }
        const float2 gb = *(const float2*)(bgo + c2);
        #pragma unroll
        for (int r = 0; r < 8; r++) {
            float l0, l1; unpack2(ao[r], l0, l1);
            *(float2*)(g_go + (size_t)(rowbase + r0 + r) * C + c2)
                = make_float2(sigm(l0 + gb.x), sigm(l1 + gb.y));
        }
    }
}

// ============================================================================
// Kernel B: per-channel 512x512x512 NT GEMM via mma.sync (HMMA bf16),
// hi/lo split 3-pass, fp32 accumulate. CTA = 128x128 tile of one channel.
// 8 warps: warp tile 64x32 (wm = wid&1, wn = wid>>1). K chunks of 64.
// smem per chunk: Ahi|Alo|Bhi|Blo, each 128x64 bf16 sw128-swizzled = 64KB.
// ============================================================================
#define KB_TILE 16384
#define KB_SMEM (4 * KB_TILE)

__global__ __launch_bounds__(256, 1)
void kB()
{
    extern __shared__ __align__(1024) char smem[];
    const u32 sb = smem_u32(smem);
    const u32 sAh = sb, sAl = sb + KB_TILE, sBh = sb + 2*KB_TILE, sBl = sb + 3*KB_TILE;
    const int tid = threadIdx.x;
    const int wid = tid >> 5, lane = tid & 31;
    const int i0 = (blockIdx.x & 3) * 128;
    const int j0 = (blockIdx.x >> 2) * 128;
    const int wm = (wid & 1) * 64;       // warp row offset in tile
    const int wn = (wid >> 1) * 32;      // warp col offset in tile
    const float* A = g_af + (size_t)blockIdx.y * PLANE + (size_t)i0 * NN;
    const float* B = g_bf + (size_t)blockIdx.y * PLANE + (size_t)j0 * NN;

    float acc[4][4][4];
    #pragma unroll
    for (int mi = 0; mi < 4; mi++)
        #pragma unroll
        for (int ni = 0; ni < 4; ni++)
            #pragma unroll
            for (int q = 0; q < 4; q++) acc[mi][ni][q] = 0.0f;

    // precomputed ldmatrix lane addressing
    const int a_row = (lane & 7) + ((lane >> 3) & 1) * 8;   // + mi*16 + wm
    const int a_kb  = (lane >> 4) * 8;                      // + kf*16
    const int b_row = (lane & 7) + (lane >> 4) * 8;         // + nb*16 + wn
    const int b_kb  = ((lane >> 3) & 1) * 8;                // + kf*16

    #pragma unroll 1
    for (int ck = 0; ck < 8; ck++) {
        const int k0 = ck * 64;
        __syncthreads();
        // ---- load fp32, split into bf16 hi/lo, store swizzled ----
        #pragma unroll
        for (int m = 0; m < 8; m++) {
            const int id  = tid + 256 * m;       // 0..2047
            const int row = id >> 4;
            const int k4  = (id & 15) * 4;
            const u32 off = sw128((u32)(row * 128 + k4 * 2));
            float4 fa = *(const float4*)(A + row * NN + k0 + k4);
            float4 fb = *(const float4*)(B + row * NN + k0 + k4);
            u32 h0 = bf16x2(fa.y, fa.x), h1 = bf16x2(fa.w, fa.z);
            u32 l0 = bf16x2(fa.y - __uint_as_float(h0 & 0xFFFF0000u),
                            fa.x - __uint_as_float(h0 << 16));
            u32 l1 = bf16x2(fa.w - __uint_as_float(h1 & 0xFFFF0000u),
                            fa.z - __uint_as_float(h1 << 16));
            asm volatile("st.shared.v2.b32 [%0], {%1,%2};" :: "r"(sAh + off), "r"(h0), "r"(h1) : "memory");
            asm volatile("st.shared.v2.b32 [%0], {%1,%2};" :: "r"(sAl + off), "r"(l0), "r"(l1) : "memory");
            h0 = bf16x2(fb.y, fb.x); h1 = bf16x2(fb.w, fb.z);
            l0 = bf16x2(fb.y - __uint_as_float(h0 & 0xFFFF0000u),
                        fb.x - __uint_as_float(h0 << 16));
            l1 = bf16x2(fb.w - __uint_as_float(h1 & 0xFFFF0000u),
                        fb.z - __uint_as_float(h1 << 16));
            asm volatile("st.shared.v2.b32 [%0], {%1,%2};" :: "r"(sBh + off), "r"(h0), "r"(h1) : "memory");
            asm volatile("st.shared.v2.b32 [%0], {%1,%2};" :: "r"(sBl + off), "r"(l0), "r"(l1) : "memory");
        }
        __syncthreads();

        // ---- MMA over 4 k-frags of 16 ----
        #pragma unroll
        for (int kf = 0; kf < 4; kf++) {
            u32 Ah[4][4], Al[4][4], Bh[2][4], Bl[2][4];
            #pragma unroll
            for (int mi = 0; mi < 4; mi++) {
                const u32 off = sw128((u32)((wm + mi * 16 + a_row) * 128 + (kf * 16 + a_kb) * 2));
                ldsm4(sAh + off, Ah[mi]);
                ldsm4(sAl + off, Al[mi]);
            }
            #pragma unroll
            for (int nb = 0; nb < 2; nb++) {
                const u32 off = sw128((u32)((wn + nb * 16 + b_row) * 128 + (kf * 16 + b_kb) * 2));
                ldsm4(sBh + off, Bh[nb]);
                ldsm4(sBl + off, Bl[nb]);
            }
            #pragma unroll
            for (int mi = 0; mi < 4; mi++)
                #pragma unroll
                for (int ni = 0; ni < 4; ni++) {
                    const u32* bh = Bh[ni >> 1] + (ni & 1) * 2;
                    const u32* bl = Bl[ni >> 1] + (ni & 1) * 2;
                    mma_bf16(acc[mi][ni], Ah[mi], bh);
                    mma_bf16(acc[mi][ni], Ah[mi], bl);
                    mma_bf16(acc[mi][ni], Al[mi], bh);
                }
        }
    }

    // ---- epilogue: fp32 tile -> g_kf plane ----
    float* dst = g_kf + (size_t)blockIdx.y * PLANE;
    #pragma unroll
    for (int mi = 0; mi < 4; mi++) {
        const int rbase = i0 + wm + mi * 16 + (lane >> 2);
        #pragma unroll
        for (int ni = 0; ni < 4; ni++) {
            const int col = j0 + wn + ni * 8 + (lane & 3) * 2;
            *(float2*)(dst + (size_t)rbase * NN + col)
                = make_float2(acc[mi][ni][0], acc[mi][ni][1]);
            *(float2*)(dst + (size_t)(rbase + 8) * NN + col)
                = make_float2(acc[mi][ni][2], acc[mi][ni][3]);
        }
    }
}

// ============================================================================
// Kernel C: out = go * (LN(k) @ Wo + bo). Reads g_kf planes coalesced.
// ============================================================================
__global__ __launch_bounds__(256)
void kC(const float* __restrict__ go_, const float* __restrict__ bo_,
        const float* __restrict__ Wo,  const float* __restrict__ bo,
        float* __restrict__ out)
{
    __shared__ __align__(16) u64 knd[32 * ZST];
    const int tid = threadIdx.x;
    const int rowbase = blockIdx.x * 32;

    { // load planes -> duplicated smem
        const int row = tid & 31;
        #pragma unroll
        for (int m = 0; m < 16; m++) {
            const int c = (tid >> 5) + m * 8;
            const float v = g_kf[(size_t)c * PLANE + rowbase + row];
            knd[row * ZST + c] = pack2(v, v);
        }
    }
    __syncthreads();
    { // LN stats + normalize in place
        const int w = tid >> 5, lane = tid & 31;
        #pragma unroll
        for (int rr = 0; rr < 4; rr++) {
            const int r = 4 * w + rr;
            float x[4];
            #pragma unroll
            for (int m = 0; m < 4; m++) {
                float lo, hi; unpack2(knd[r * ZST + lane + 32 * m], lo, hi);
                x[m] = lo;
            }
            float s = x[0] + x[1] + x[2] + x[3];
            float q = x[0]*x[0] + x[1]*x[1] + x[2]*x[2] + x[3]*x[3];
            #pragma unroll
            for (int o = 16; o; o >>= 1) {
                s += __shfl_xor_sync(~0u, s, o);
                q += __shfl_xor_sync(~0u, q, o);
            }
            const float mean = s * (1.0f / C);
            const float rstd = rsqrtf(q * (1.0f / C) - mean * mean + 1e-5f);
            #pragma unroll
            for (int m = 0; m < 4; m++) {
                const int c = lane + 32 * m;
                const float v = (x[m] - mean) * rstd * go_[c] + bo_[c];
                knd[r * ZST + c] = pack2(v, v);
            }
        }
    }
    __syncthreads();

    const int c2 = (tid & 63) * 2;
    const int r0 = (tid >> 6) * 8;
    const u64* kr = knd + r0 * ZST;

    u64 ao[8];
    #pragma unroll
    for (int r = 0; r < 8; r++) ao[r] = 0;
    #pragma unroll 2
    for (int k = 0; k < C; k += 2) {
        const u64 wa = *(const u64*)(Wo + k * C + c2);
        const u64 wb = *(const u64*)(Wo + (k + 1) * C + c2);
        #pragma unroll
        for (int r = 0; r < 8; r++) {
            const ulonglong2 zz = *(const ulonglong2*)(kr + r * ZST + k);
            ao[r] = ffma2(zz.x, wa, ao[r]); ao[r] = ffma2(zz.y, wb, ao[r]);
        }
    }
    const float2 bb2 = *(const float2*)(bo + c2);
    #pragma unroll
    for (int r = 0; r < 8; r++) {
        float l0, l1; unpack2(ao[r], l0, l1);
        const size_t row = rowbase + r0 + r;
        const float2 gg = *(const float2*)(g_go + row * C + c2);
        *(float2*)(out + row * C + c2)
            = make_float2(gg.x * (l0 + bb2.x), gg.y * (l1 + bb2.y));
    }
}

// ============================================================================
extern "C" void kernel_launch(void* const* d_in, const int* in_sizes, int n_in,
                              void* d_out, int out_size)
{
    const float*         z    = (const float*)d_in[0];
    const unsigned char* mask = (const unsigned char*)d_in[1];
    const float* gin = (const float*)d_in[2],  *bin = (const float*)d_in[3];
    const float* Wa  = (const float*)d_in[4],  *ba  = (const float*)d_in[5];
    const float* Wga = (const float*)d_in[6],  *bga = (const float*)d_in[7];
    const float* Wb  = (const float*)d_in[8],  *bb  = (const float*)d_in[9];
    const float* Wgb = (const float*)d_in[10], *bgb = (const float*)d_in[11];
    const float* g_o = (const float*)d_in[12], *b_o = (const float*)d_in[13];
    const float* Wgo = (const float*)d_in[14], *bgo = (const float*)d_in[15];
    const float* Wo  = (const float*)d_in[16], *bo  = (const float*)d_in[17];
    float* out = (float*)d_out;

    static int kb_attr_set = 0;
    if (!kb_attr_set) {
        cudaFuncSetAttribute(kB, cudaFuncAttributeMaxDynamicSharedMemorySize, KB_SMEM);
        kb_attr_set = 1;
    }

    kA<<<NROWS / 32, 256>>>(z, mask, gin, bin, Wa, ba, Wga, bga,
                            Wb, bb, Wgb, bgb, Wgo, bgo);
    kB<<<dim3(16, C), 256, KB_SMEM>>>();
    kC<<<NROWS / 32, 256>>>(g_o, b_o, Wo, bo, out);
}

// round 6
// speedup vs baseline: 2.0018x; 1.5652x over previous
#include <cuda_runtime.h>

typedef unsigned long long u64;
typedef unsigned int u32;

#define NN 512
#define C 128
#define NROWS (NN * NN)
#define PLANE ((size_t)NROWS)

// ---- scratch ----
__device__ u32  g_znh[(size_t)NROWS * 64];   // zn hi bf16 pairs, row-major [row][64 u32]
__device__ u32  g_znl[(size_t)NROWS * 64];   // zn lo
__device__ u32  g_wth[5 * 128 * 64];         // W^T hi bf16 pairs [mat][n][64 u32]
__device__ u32  g_wtl[5 * 128 * 64];
__device__ float g_af[(size_t)C * NROWS];    // a planes [c][row]
__device__ float g_bf[(size_t)C * NROWS];
__device__ float g_go[(size_t)NROWS * C];    // [row][c]
__device__ float g_kf[(size_t)C * NROWS];    // [c][i*512+j]

// ---- helpers ----
__device__ __forceinline__ u64 pack2(float lo, float hi) {
    u64 r; asm("mov.b64 %0, {%1, %2};" : "=l"(r) : "f"(lo), "f"(hi)); return r;
}
__device__ __forceinline__ void unpack2(u64 v, float& lo, float& hi) {
    asm("mov.b64 {%0, %1}, %2;" : "=f"(lo), "=f"(hi) : "l"(v));
}
__device__ __forceinline__ u64 ffma2(u64 a, u64 b, u64 c) {
    u64 d; asm("fma.rn.f32x2 %0, %1, %2, %3;" : "=l"(d) : "l"(a), "l"(b), "l"(c)); return d;
}
__device__ __forceinline__ float sigm(float x) { return 1.0f / (1.0f + __expf(-x)); }
__device__ __forceinline__ u32 bf16x2(float hi_val, float lo_val) {  // {upper=hi_val, lower=lo_val}
    u32 r; asm("cvt.rn.bf16x2.f32 %0, %1, %2;" : "=r"(r) : "f"(hi_val), "f"(lo_val)); return r;
}
__device__ __forceinline__ u32 smem_u32(const void* p) {
    u32 a; asm("{ .reg .u64 t; cvta.to.shared.u64 t, %1; cvt.u32.u64 %0, t; }" : "=r"(a) : "l"(p));
    return a;
}
__device__ __forceinline__ u32 sw128(u32 x) { return x ^ ((x >> 3) & 0x70); }

__device__ __forceinline__ void ldsm4(u32 addr, u32* r) {
    asm volatile("ldmatrix.sync.aligned.m8n8.x4.shared.b16 {%0,%1,%2,%3}, [%4];"
        : "=r"(r[0]), "=r"(r[1]), "=r"(r[2]), "=r"(r[3]) : "r"(addr));
}
__device__ __forceinline__ void mma_bf16(float* c, const u32* a, const u32* b) {
    asm volatile("mma.sync.aligned.m16n8k16.row.col.f32.bf16.bf16.f32 "
        "{%0,%1,%2,%3}, {%4,%5,%6,%7}, {%8,%9}, {%0,%1,%2,%3};"
        : "+f"(c[0]), "+f"(c[1]), "+f"(c[2]), "+f"(c[3])
        : "r"(a[0]), "r"(a[1]), "r"(a[2]), "r"(a[3]), "r"(b[0]), "r"(b[1]));
}

__device__ __forceinline__ int detect_mask_is_int32(const unsigned char* m) {
    const uint4* p = (const uint4*)m;
    unsigned acc = 0;
    #pragma unroll
    for (int i = 0; i < 4; i++) { uint4 v = p[i]; acc |= v.x | v.y | v.z | v.w; }
    return (acc & 0xFFFFFF00u) == 0u;
}
__device__ __forceinline__ float mask_val(const unsigned char* m, int row, int i32) {
    int v = i32 ? ((const int*)m)[row] : (int)m[row];
    return v ? 0.0f : 1.0f;
}

// split fp32 pair -> bf16 hi pair + lo pair
__device__ __forceinline__ void split2(float v0, float v1, u32& h, u32& l) {
    h = bf16x2(v1, v0);
    const float h0 = __uint_as_float(h << 16);
    const float h1 = __uint_as_float(h & 0xFFFF0000u);
    l = bf16x2(v1 - h1, v0 - h0);
}

// ============================================================================
// kW: transpose 5 weight matrices [k][n] -> bf16 hi/lo [mat][n][k]. grid=5.
// ============================================================================
__global__ __launch_bounds__(256)
void kW(const float* __restrict__ Wa, const float* __restrict__ Wga,
        const float* __restrict__ Wb, const float* __restrict__ Wgb,
        const float* __restrict__ Wgo)
{
    const float* Ws[5] = {Wa, Wga, Wb, Wgb, Wgo};
    const int mat = blockIdx.x;
    const float* W = Ws[mat];
    for (int idx = threadIdx.x; idx < 128 * 64; idx += 256) {
        const int n = idx >> 6, k2 = idx & 63;
        const float x0 = W[(2 * k2) * 128 + n];
        const float x1 = W[(2 * k2 + 1) * 128 + n];
        u32 h, l; split2(x0, x1, h, l);
        g_wth[mat * 8192 + n * 64 + k2] = h;
        g_wtl[mat * 8192 + n * 64 + k2] = l;
    }
}

// ============================================================================
// kPrep: LN(z) -> bf16 hi/lo zn planes, row-major. 32 rows/block.
// ============================================================================
__global__ __launch_bounds__(256)
void kPrep(const float* __restrict__ z,
           const float* __restrict__ gin, const float* __restrict__ bin)
{
    const int tid = threadIdx.x;
    const int w = tid >> 5, lane = tid & 31;
    const int rowbase = blockIdx.x * 32;
    #pragma unroll
    for (int rr = 0; rr < 4; rr++) {
        const int row = rowbase + 4 * w + rr;
        float4 x = *(const float4*)(z + (size_t)row * C + lane * 4);
        float s = x.x + x.y + x.z + x.w;
        float q = x.x*x.x + x.y*x.y + x.z*x.z + x.w*x.w;
        #pragma unroll
        for (int o = 16; o; o >>= 1) {
            s += __shfl_xor_sync(~0u, s, o);
            q += __shfl_xor_sync(~0u, q, o);
        }
        const float mean = s * (1.0f / C);
        const float rstd = rsqrtf(q * (1.0f / C) - mean * mean + 1e-5f);
        float4 g4 = *(const float4*)(gin + lane * 4);
        float4 b4 = *(const float4*)(bin + lane * 4);
        const float v0 = (x.x - mean) * rstd * g4.x + b4.x;
        const float v1 = (x.y - mean) * rstd * g4.y + b4.y;
        const float v2 = (x.z - mean) * rstd * g4.z + b4.z;
        const float v3 = (x.w - mean) * rstd * g4.w + b4.w;
        u32 h0, l0, h1, l1;
        split2(v0, v1, h0, l0);
        split2(v2, v3, h1, l1);
        *(uint2*)(g_znh + (size_t)row * 64 + lane * 2) = make_uint2(h0, h1);
        *(uint2*)(g_znl + (size_t)row * 64 + lane * 2) = make_uint2(l0, l1);
    }
}

// ============================================================================
// kProj: HMMA projections. grid = (2048 M-tiles, 3 jobs), 512 threads.
//   job 0: a = mask*sigm(zn@Wga+bga)*(zn@Wa+ba) -> g_af plane
//   job 1: b (Wb, Wgb) -> g_bf plane
//   job 2: go = sigm(zn@Wgo+bgo) -> g_go row-major
// smem: A hi/lo (64KB) + B0 hi/lo (64KB) + B1 hi/lo (64KB) = 192KB.
// Each bf16 tile = 2 halves of [128 rows x 64k], sw128 within half.
// ============================================================================
#define PJ_SMEM (192 * 1024)
__global__ __launch_bounds__(512, 1)
void kProj(const unsigned char* __restrict__ mask,
           const float* __restrict__ ba,  const float* __restrict__ bga,
           const float* __restrict__ bb,  const float* __restrict__ bgb,
           const float* __restrict__ bgo)
{
    extern __shared__ __align__(1024) char smem[];
    __shared__ float msk[128];
    __shared__ int s_mi32;
    const u32 sb = smem_u32(smem);
    const u32 sAh = sb,            sAl = sb + 32*1024;
    const u32 sB0h = sb + 64*1024, sB0l = sb + 96*1024;
    const u32 sB1h = sb + 128*1024, sB1l = sb + 160*1024;
    const int tid = threadIdx.x;
    const int wid = tid >> 5, lane = tid & 31;
    const int job = blockIdx.y;
    const int rowbase = blockIdx.x * 128;
    const int m0 = (job < 2) ? 2 * job : 4;

    if (tid == 0) s_mi32 = detect_mask_is_int32(mask);

    // ---- load A (zn hi/lo) ----
    #pragma unroll
    for (int m = 0; m < 4; m++) {
        const int id = tid + 512 * m;            // 0..2047
        const int row = id >> 4, qq = id & 15;   // 16 uint4 per row
        const u32 off = (qq >> 3) * 16384 + sw128((u32)(row * 128 + (qq & 7) * 16));
        uint4 vh = *(const uint4*)(g_znh + (size_t)(rowbase + row) * 64 + qq * 4);
        uint4 vl = *(const uint4*)(g_znl + (size_t)(rowbase + row) * 64 + qq * 4);
        *(uint4*)(smem + (sAh - sb) + off) = vh;
        *(uint4*)(smem + (sAl - sb) + off) = vl;
    }
    // ---- load B (weights) ----
    {
        const int id = tid;                      // 2048 uint4 per matrix, 4 per thread
        #pragma unroll
        for (int m = 0; m < 4; m++) {
            const int i2 = id + 512 * m;
            const int n = i2 >> 4, qq = i2 & 15;
            const u32 off = (qq >> 3) * 16384 + sw128((u32)(n * 128 + (qq & 7) * 16));
            uint4 vh = *(const uint4*)(g_wth + m0 * 8192 + n * 64 + qq * 4);
            uint4 vl = *(const uint4*)(g_wtl + m0 * 8192 + n * 64 + qq * 4);
            *(uint4*)(smem + (sB0h - sb) + off) = vh;
            *(uint4*)(smem + (sB0l - sb) + off) = vl;
            if (job < 2) {
                vh = *(const uint4*)(g_wth + (m0 + 1) * 8192 + n * 64 + qq * 4);
                vl = *(const uint4*)(g_wtl + (m0 + 1) * 8192 + n * 64 + qq * 4);
                *(uint4*)(smem + (sB1h - sb) + off) = vh;
                *(uint4*)(smem + (sB1l - sb) + off) = vl;
            }
        }
    }
    __syncthreads();
    if (tid < 128) msk[tid] = mask_val(mask, rowbase + tid, s_mi32);

    // ---- MMA ----
    const int wm = (wid & 3) * 32;    // warp row offset
    const int wn = (wid >> 2) * 32;   // warp col offset
    const int a_row = (lane & 7) + ((lane >> 3) & 1) * 8;
    const int a_kb  = (lane >> 4) * 8;
    const int b_row = (lane & 7) + (lane >> 4) * 8;
    const int b_kb  = ((lane >> 3) & 1) * 8;

    float accL[2][4][4], accG[2][4][4];
    #pragma unroll
    for (int mi = 0; mi < 2; mi++)
        #pragma unroll
        for (int ni = 0; ni < 4; ni++)
            #pragma unroll
            for (int q = 0; q < 4; q++) { accL[mi][ni][q] = 0.f; accG[mi][ni][q] = 0.f; }

    #pragma unroll
    for (int kf = 0; kf < 8; kf++) {
        const u32 hoff = (kf >> 2) * 16384;
        const int kp = (kf & 3) * 16;
        u32 Ah[2][4], Al[2][4];
        #pragma unroll
        for (int mi = 0; mi < 2; mi++) {
            const u32 o = hoff + sw128((u32)((wm + mi * 16 + a_row) * 128 + (kp + a_kb) * 2));
            ldsm4(sAh + o, Ah[mi]);
            ldsm4(sAl + o, Al[mi]);
        }
        u32 Bh[2][4], Bl[2][4];
        #pragma unroll
        for (int nb = 0; nb < 2; nb++) {
            const u32 o = hoff + sw128((u32)((wn + nb * 16 + b_row) * 128 + (kp + b_kb) * 2));
            ldsm4(sB0h + o, Bh[nb]);
            ldsm4(sB0l + o, Bl[nb]);
        }
        #pragma unroll
        for (int mi = 0; mi < 2; mi++)
            #pragma unroll
            for (int ni = 0; ni < 4; ni++) {
                const u32* bh = Bh[ni >> 1] + (ni & 1) * 2;
                const u32* bl = Bl[ni >> 1] + (ni & 1) * 2;
                mma_bf16(accL[mi][ni], Ah[mi], bh);
                mma_bf16(accL[mi][ni], Ah[mi], bl);
                mma_bf16(accL[mi][ni], Al[mi], bh);
            }
        if (job < 2) {
            #pragma unroll
            for (int nb = 0; nb < 2; nb++) {
                const u32 o = hoff + sw128((u32)((wn + nb * 16 + b_row) * 128 + (kp + b_kb) * 2));
                ldsm4(sB1h + o, Bh[nb]);
                ldsm4(sB1l + o, Bl[nb]);
            }
            #pragma unroll
            for (int mi = 0; mi < 2; mi++)
                #pragma unroll
                for (int ni = 0; ni < 4; ni++) {
                    const u32* bh = Bh[ni >> 1] + (ni & 1) * 2;
                    const u32* bl = Bl[ni >> 1] + (ni & 1) * 2;
                    mma_bf16(accG[mi][ni], Ah[mi], bh);
                    mma_bf16(accG[mi][ni], Ah[mi], bl);
                    mma_bf16(accG[mi][ni], Al[mi], bh);
                }
        }
    }
    __syncthreads();

    if (job < 2) {
        const float* bl_ = job ? bb : ba;
        const float* bg_ = job ? bgb : bga;
        float* sT = (float*)(smem + 64 * 1024);   // [c][row], stride 132
        #pragma unroll
        for (int mi = 0; mi < 2; mi++) {
            const int r0 = wm + mi * 16 + (lane >> 2);
            const int r1 = r0 + 8;
            const float mv0 = msk[r0], mv1 = msk[r1];
            #pragma unroll
            for (int ni = 0; ni < 4; ni++) {
                const int c = wn + ni * 8 + (lane & 3) * 2;
                const float bl0 = __ldg(bl_ + c), bl1 = __ldg(bl_ + c + 1);
                const float bg0 = __ldg(bg_ + c), bg1 = __ldg(bg_ + c + 1);
                sT[c * 132 + r0]       = mv0 * sigm(accG[mi][ni][0] + bg0) * (accL[mi][ni][0] + bl0);
                sT[(c + 1) * 132 + r0] = mv0 * sigm(accG[mi][ni][1] + bg1) * (accL[mi][ni][1] + bl1);
                sT[c * 132 + r1]       = mv1 * sigm(accG[mi][ni][2] + bg0) * (accL[mi][ni][2] + bl0);
                sT[(c + 1) * 132 + r1] = mv1 * sigm(accG[mi][ni][3] + bg1) * (accL[mi][ni][3] + bl1);
            }
        }
        __syncthreads();
        float* plane = job ? g_bf : g_af;
        const int c = tid >> 2;
        const int rb = (tid & 3) * 32;
        #pragma unroll
        for (int j = 0; j < 8; j++) {
            float4 v = *(float4*)(sT + c * 132 + rb + j * 4);
            *(float4*)(plane + (size_t)c * PLANE + rowbase + rb + j * 4) = v;
        }
    } else {
        #pragma unroll
        for (int mi = 0; mi < 2; mi++) {
            const int r0 = wm + mi * 16 + (lane >> 2);
            #pragma unroll
            for (int ni = 0; ni < 4; ni++) {
                const int c = wn + ni * 8 + (lane & 3) * 2;
                const float b0 = __ldg(bgo + c), b1 = __ldg(bgo + c + 1);
                *(float2*)(g_go + (size_t)(rowbase + r0) * C + c)
                    = make_float2(sigm(accL[mi][ni][0] + b0), sigm(accL[mi][ni][1] + b1));
                *(float2*)(g_go + (size_t)(rowbase + r0 + 8) * C + c)
                    = make_float2(sigm(accL[mi][ni][2] + b0), sigm(accL[mi][ni][3] + b1));
            }
        }
    }
}

// ============================================================================
// Kernel B: per-channel 512x512x512 NT GEMM via HMMA bf16, hi/lo 3-pass.
// (unchanged from round 5 — known good)
// ============================================================================
#define KB_TILE 16384
#define KB_SMEM (4 * KB_TILE)

__global__ __launch_bounds__(256, 1)
void kB()
{
    extern __shared__ __align__(1024) char smem[];
    const u32 sb = smem_u32(smem);
    const u32 sAh = sb, sAl = sb + KB_TILE, sBh = sb + 2*KB_TILE, sBl = sb + 3*KB_TILE;
    const int tid = threadIdx.x;
    const int wid = tid >> 5, lane = tid & 31;
    const int i0 = (blockIdx.x & 3) * 128;
    const int j0 = (blockIdx.x >> 2) * 128;
    const int wm = (wid & 1) * 64;
    const int wn = (wid >> 1) * 32;
    const float* A = g_af + (size_t)blockIdx.y * PLANE + (size_t)i0 * NN;
    const float* B = g_bf + (size_t)blockIdx.y * PLANE + (size_t)j0 * NN;

    float acc[4][4][4];
    #pragma unroll
    for (int mi = 0; mi < 4; mi++)
        #pragma unroll
        for (int ni = 0; ni < 4; ni++)
            #pragma unroll
            for (int q = 0; q < 4; q++) acc[mi][ni][q] = 0.0f;

    const int a_row = (lane & 7) + ((lane >> 3) & 1) * 8;
    const int a_kb  = (lane >> 4) * 8;
    const int b_row = (lane & 7) + (lane >> 4) * 8;
    const int b_kb  = ((lane >> 3) & 1) * 8;

    #pragma unroll 1
    for (int ck = 0; ck < 8; ck++) {
        const int k0 = ck * 64;
        __syncthreads();
        #pragma unroll
        for (int m = 0; m < 8; m++) {
            const int id  = tid + 256 * m;
            const int row = id >> 4;
            const int k4  = (id & 15) * 4;
            const u32 off = sw128((u32)(row * 128 + k4 * 2));
            float4 fa = *(const float4*)(A + row * NN + k0 + k4);
            float4 fb = *(const float4*)(B + row * NN + k0 + k4);
            u32 h0, l0, h1, l1;
            split2(fa.x, fa.y, h0, l0); split2(fa.z, fa.w, h1, l1);
            asm volatile("st.shared.v2.b32 [%0], {%1,%2};" :: "r"(sAh + off), "r"(h0), "r"(h1) : "memory");
            asm volatile("st.shared.v2.b32 [%0], {%1,%2};" :: "r"(sAl + off), "r"(l0), "r"(l1) : "memory");
            split2(fb.x, fb.y, h0, l0); split2(fb.z, fb.w, h1, l1);
            asm volatile("st.shared.v2.b32 [%0], {%1,%2};" :: "r"(sBh + off), "r"(h0), "r"(h1) : "memory");
            asm volatile("st.shared.v2.b32 [%0], {%1,%2};" :: "r"(sBl + off), "r"(l0), "r"(l1) : "memory");
        }
        __syncthreads();

        #pragma unroll
        for (int kf = 0; kf < 4; kf++) {
            u32 Ah[4][4], Al[4][4], Bh[2][4], Bl[2][4];
            #pragma unroll
            for (int mi = 0; mi < 4; mi++) {
                const u32 off = sw128((u32)((wm + mi * 16 + a_row) * 128 + (kf * 16 + a_kb) * 2));
                ldsm4(sAh + off, Ah[mi]);
                ldsm4(sAl + off, Al[mi]);
            }
            #pragma unroll
            for (int nb = 0; nb < 2; nb++) {
                const u32 off = sw128((u32)((wn + nb * 16 + b_row) * 128 + (kf * 16 + b_kb) * 2));
                ldsm4(sBh + off, Bh[nb]);
                ldsm4(sBl + off, Bl[nb]);
            }
            #pragma unroll
            for (int mi = 0; mi < 4; mi++)
                #pragma unroll
                for (int ni = 0; ni < 4; ni++) {
                    const u32* bh = Bh[ni >> 1] + (ni & 1) * 2;
                    const u32* bl = Bl[ni >> 1] + (ni & 1) * 2;
                    mma_bf16(acc[mi][ni], Ah[mi], bh);
                    mma_bf16(acc[mi][ni], Ah[mi], bl);
                    mma_bf16(acc[mi][ni], Al[mi], bh);
                }
        }
    }

    float* dst = g_kf + (size_t)blockIdx.y * PLANE;
    #pragma unroll
    for (int mi = 0; mi < 4; mi++) {
        const int rbase = i0 + wm + mi * 16 + (lane >> 2);
        #pragma unroll
        for (int ni = 0; ni < 4; ni++) {
            const int col = j0 + wn + ni * 8 + (lane & 3) * 2;
            *(float2*)(dst + (size_t)rbase * NN + col)
                = make_float2(acc[mi][ni][0], acc[mi][ni][1]);
            *(float2*)(dst + (size_t)(rbase + 8) * NN + col)
                = make_float2(acc[mi][ni][2], acc[mi][ni][3]);
        }
    }
}

// ============================================================================
// Kernel C: out = go * (LN(k) @ Wo + bo). (unchanged)
// ============================================================================
#define ZST 130
__global__ __launch_bounds__(256)
void kC(const float* __restrict__ go_, const float* __restrict__ bo_,
        const float* __restrict__ Wo,  const float* __restrict__ bo,
        float* __restrict__ out)
{
    __shared__ __align__(16) u64 knd[32 * ZST];
    const int tid = threadIdx.x;
    const int rowbase = blockIdx.x * 32;

    {
        const int row = tid & 31;
        #pragma unroll
        for (int m = 0; m < 16; m++) {
            const int c = (tid >> 5) + m * 8;
            const float v = g_kf[(size_t)c * PLANE + rowbase + row];
            knd[row * ZST + c] = pack2(v, v);
        }
    }
    __syncthreads();
    {
        const int w = tid >> 5, lane = tid & 31;
        #pragma unroll
        for (int rr = 0; rr < 4; rr++) {
            const int r = 4 * w + rr;
            float x[4];
            #pragma unroll
            for (int m = 0; m < 4; m++) {
                float lo, hi; unpack2(knd[r * ZST + lane + 32 * m], lo, hi);
                x[m] = lo;
            }
            float s = x[0] + x[1] + x[2] + x[3];
            float q = x[0]*x[0] + x[1]*x[1] + x[2]*x[2] + x[3]*x[3];
            #pragma unroll
            for (int o = 16; o; o >>= 1) {
                s += __shfl_xor_sync(~0u, s, o);
                q += __shfl_xor_sync(~0u, q, o);
            }
            const float mean = s * (1.0f / C);
            const float rstd = rsqrtf(q * (1.0f / C) - mean * mean + 1e-5f);
            #pragma unroll
            for (int m = 0; m < 4; m++) {
                const int c = lane + 32 * m;
                const float v = (x[m] - mean) * rstd * go_[c] + bo_[c];
                knd[r * ZST + c] = pack2(v, v);
            }
        }
    }
    __syncthreads();

    const int c2 = (tid & 63) * 2;
    const int r0 = (tid >> 6) * 8;
    const u64* kr = knd + r0 * ZST;

    u64 ao[8];
    #pragma unroll
    for (int r = 0; r < 8; r++) ao[r] = 0;
    #pragma unroll 2
    for (int k = 0; k < C; k += 2) {
        const u64 wa = *(const u64*)(Wo + k * C + c2);
        const u64 wb = *(const u64*)(Wo + (k + 1) * C + c2);
        #pragma unroll
        for (int r = 0; r < 8; r++) {
            const ulonglong2 zz = *(const ulonglong2*)(kr + r * ZST + k);
            ao[r] = ffma2(zz.x, wa, ao[r]); ao[r] = ffma2(zz.y, wb, ao[r]);
        }
    }
    const float2 bb2 = *(const float2*)(bo + c2);
    #pragma unroll
    for (int r = 0; r < 8; r++) {
        float l0, l1; unpack2(ao[r], l0, l1);
        const size_t row = rowbase + r0 + r;
        const float2 gg = *(const float2*)(g_go + row * C + c2);
        *(float2*)(out + row * C + c2)
            = make_float2(gg.x * (l0 + bb2.x), gg.y * (l1 + bb2.y));
    }
}

// ============================================================================
extern "C" void kernel_launch(void* const* d_in, const int* in_sizes, int n_in,
                              void* d_out, int out_size)
{
    const float*         z    = (const float*)d_in[0];
    const unsigned char* mask = (const unsigned char*)d_in[1];
    const float* gin = (const float*)d_in[2],  *bin = (const float*)d_in[3];
    const float* Wa  = (const float*)d_in[4],  *ba  = (const float*)d_in[5];
    const float* Wga = (const float*)d_in[6],  *bga = (const float*)d_in[7];
    const float* Wb  = (const float*)d_in[8],  *bb  = (const float*)d_in[9];
    const float* Wgb = (const float*)d_in[10], *bgb = (const float*)d_in[11];
    const float* g_o = (const float*)d_in[12], *b_o = (const float*)d_in[13];
    const float* Wgo = (const float*)d_in[14], *bgo = (const float*)d_in[15];
    const float* Wo  = (const float*)d_in[16], *bo  = (const float*)d_in[17];
    float* out = (float*)d_out;

    static int attr_set = 0;
    if (!attr_set) {
        cudaFuncSetAttribute(kB, cudaFuncAttributeMaxDynamicSharedMemorySize, KB_SMEM);
        cudaFuncSetAttribute(kProj, cudaFuncAttributeMaxDynamicSharedMemorySize, PJ_SMEM);
        attr_set = 1;
    }

    kW<<<5, 256>>>(Wa, Wga, Wb, Wgb, Wgo);
    kPrep<<<NROWS / 32, 256>>>(z, gin, bin);
    kProj<<<dim3(2048, 3), 512, PJ_SMEM>>>(mask, ba, bga, bb, bgb, bgo);
    kB<<<dim3(16, C), 256, KB_SMEM>>>();
    kC<<<NROWS / 32, 256>>>(g_o, b_o, Wo, bo, out);
}

// round 8
// speedup vs baseline: 2.2963x; 1.1471x over previous
#include <cuda_runtime.h>

typedef unsigned long long u64;
typedef unsigned int u32;

#define NN 512
#define C 128
#define NROWS (NN * NN)
#define PLANE ((size_t)NROWS)
#define PLANE2 ((size_t)(NROWS / 2))   // u32-pair plane size

// ---- scratch ----
__device__ u32  g_znh[(size_t)NROWS * 64];   // LN(z) hi bf16 pairs [row][64]
__device__ u32  g_znl[(size_t)NROWS * 64];
__device__ u32  g_wth[6 * 128 * 64];         // W^T hi bf16 pairs [mat][n][64]
__device__ u32  g_wtl[6 * 128 * 64];
__device__ u32  g_ah[(size_t)C * PLANE2];    // a planes bf16 pairs [c][row/2]
__device__ u32  g_al[(size_t)C * PLANE2];
__device__ u32  g_bh[(size_t)C * PLANE2];
__device__ u32  g_bl[(size_t)C * PLANE2];
__device__ float g_go[(size_t)NROWS * C];    // gate, [row][c]
__device__ float g_kf[(size_t)C * NROWS];    // einsum out fp32 [c][i*512+j]
__device__ u32  g_knh[(size_t)NROWS * 64];   // LN(k) hi bf16 pairs [row][64]
__device__ u32  g_knl[(size_t)NROWS * 64];

// ---- helpers ----
__device__ __forceinline__ float sigm(float x) { return 1.0f / (1.0f + __expf(-x)); }
__device__ __forceinline__ u32 bf16x2(float hi_val, float lo_val) {  // {upper=hi_val, lower=lo_val}
    u32 r; asm("cvt.rn.bf16x2.f32 %0, %1, %2;" : "=r"(r) : "f"(hi_val), "f"(lo_val)); return r;
}
__device__ __forceinline__ u32 smem_u32(const void* p) {
    u32 a; asm("{ .reg .u64 t; cvta.to.shared.u64 t, %1; cvt.u32.u64 %0, t; }" : "=r"(a) : "l"(p));
    return a;
}
__device__ __forceinline__ u32 sw128(u32 x) { return x ^ ((x >> 3) & 0x70); }

__device__ __forceinline__ void ldsm4(u32 addr, u32* r) {
    asm volatile("ldmatrix.sync.aligned.m8n8.x4.shared.b16 {%0,%1,%2,%3}, [%4];"
        : "=r"(r[0]), "=r"(r[1]), "=r"(r[2]), "=r"(r[3]) : "r"(addr));
}
__device__ __forceinline__ void mma_bf16(float* c, const u32* a, const u32* b) {
    asm volatile("mma.sync.aligned.m16n8k16.row.col.f32.bf16.bf16.f32 "
        "{%0,%1,%2,%3}, {%4,%5,%6,%7}, {%8,%9}, {%0,%1,%2,%3};"
        : "+f"(c[0]), "+f"(c[1]), "+f"(c[2]), "+f"(c[3])
        : "r"(a[0]), "r"(a[1]), "r"(a[2]), "r"(a[3]), "r"(b[0]), "r"(b[1]));
}
__device__ __forceinline__ void cpasync16(u32 dst, const void* src) {
    asm volatile("cp.async.cg.shared.global [%0], [%1], 16;" :: "r"(dst), "l"(src));
}

__device__ __forceinline__ int detect_mask_is_int32(const unsigned char* m) {
    const uint4* p = (const uint4*)m;
    unsigned acc = 0;
    #pragma unroll
    for (int i = 0; i < 4; i++) { uint4 v = p[i]; acc |= v.x | v.y | v.z | v.w; }
    return (acc & 0xFFFFFF00u) == 0u;
}
__device__ __forceinline__ float mask_val(const unsigned char* m, int row, int i32) {
    int v = i32 ? ((const int*)m)[row] : (int)m[row];
    return v ? 0.0f : 1.0f;
}

// split fp32 pair -> bf16 hi pair + lo pair
__device__ __forceinline__ void split2(float v0, float v1, u32& h, u32& l) {
    h = bf16x2(v1, v0);
    const float h0 = __uint_as_float(h << 16);
    const float h1 = __uint_as_float(h & 0xFFFF0000u);
    l = bf16x2(v1 - h1, v0 - h0);
}

// ============================================================================
// kW: transpose 6 weight matrices [k][n] -> bf16 hi/lo [mat][n][k]. grid=6.
// ============================================================================
__global__ __launch_bounds__(256)
void kW(const float* __restrict__ Wa, const float* __restrict__ Wga,
        const float* __restrict__ Wb, const float* __restrict__ Wgb,
        const float* __restrict__ Wgo, const float* __restrict__ Wo)
{
    const float* Ws[6] = {Wa, Wga, Wb, Wgb, Wgo, Wo};
    const int mat = blockIdx.x;
    const float* W = Ws[mat];
    for (int idx = threadIdx.x; idx < 128 * 64; idx += 256) {
        const int n = idx >> 6, k2 = idx & 63;
        const float x0 = W[(2 * k2) * 128 + n];
        const float x1 = W[(2 * k2 + 1) * 128 + n];
        u32 h, l; split2(x0, x1, h, l);
        g_wth[mat * 8192 + n * 64 + k2] = h;
        g_wtl[mat * 8192 + n * 64 + k2] = l;
    }
}

// ============================================================================
// kPrep: LN(z) -> bf16 hi/lo zn planes, row-major. 32 rows/block.
// ============================================================================
__global__ __launch_bounds__(256)
void kPrep(const float* __restrict__ z,
           const float* __restrict__ gin, const float* __restrict__ bin)
{
    const int tid = threadIdx.x;
    const int w = tid >> 5, lane = tid & 31;
    const int rowbase = blockIdx.x * 32;
    #pragma unroll
    for (int rr = 0; rr < 4; rr++) {
        const int row = rowbase + 4 * w + rr;
        float4 x = *(const float4*)(z + (size_t)row * C + lane * 4);
        float s = x.x + x.y + x.z + x.w;
        float q = x.x*x.x + x.y*x.y + x.z*x.z + x.w*x.w;
        #pragma unroll
        for (int o = 16; o; o >>= 1) {
            s += __shfl_xor_sync(~0u, s, o);
            q += __shfl_xor_sync(~0u, q, o);
        }
        const float mean = s * (1.0f / C);
        const float rstd = rsqrtf(q * (1.0f / C) - mean * mean + 1e-5f);
        float4 g4 = *(const float4*)(gin + lane * 4);
        float4 b4 = *(const float4*)(bin + lane * 4);
        const float v0 = (x.x - mean) * rstd * g4.x + b4.x;
        const float v1 = (x.y - mean) * rstd * g4.y + b4.y;
        const float v2 = (x.z - mean) * rstd * g4.z + b4.z;
        const float v3 = (x.w - mean) * rstd * g4.w + b4.w;
        u32 h0, l0, h1, l1;
        split2(v0, v1, h0, l0);
        split2(v2, v3, h1, l1);
        *(uint2*)(g_znh + (size_t)row * 64 + lane * 2) = make_uint2(h0, h1);
        *(uint2*)(g_znl + (size_t)row * 64 + lane * 2) = make_uint2(l0, l1);
    }
}

// ============================================================================
// kProj: HMMA projections. grid = (2048 M-tiles, 3 jobs), 512 threads.
//   job 0: a -> g_ah/g_al bf16 planes;  job 1: b -> g_bh/g_bl;  job 2: go.
// ============================================================================
#define PJ_SMEM (192 * 1024)
__global__ __launch_bounds__(512, 1)
void kProj(const unsigned char* __restrict__ mask,
           const float* __restrict__ ba,  const float* __restrict__ bga,
           const float* __restrict__ bb,  const float* __restrict__ bgb,
           const float* __restrict__ bgo)
{
    extern __shared__ __align__(1024) char smem[];
    __shared__ float msk[128];
    __shared__ int s_mi32;
    const u32 sb = smem_u32(smem);
    const u32 sAh = sb,             sAl = sb + 32*1024;
    const u32 sB0h = sb + 64*1024,  sB0l = sb + 96*1024;
    const u32 sB1h = sb + 128*1024, sB1l = sb + 160*1024;
    const int tid = threadIdx.x;
    const int wid = tid >> 5, lane = tid & 31;
    const int job = blockIdx.y;
    const int rowbase = blockIdx.x * 128;
    const int m0 = (job < 2) ? 2 * job : 4;

    if (tid == 0) s_mi32 = detect_mask_is_int32(mask);

    // ---- load A (zn hi/lo) ----
    #pragma unroll
    for (int m = 0; m < 4; m++) {
        const int id = tid + 512 * m;
        const int row = id >> 4, qq = id & 15;
        const u32 off = (qq >> 3) * 16384 + sw128((u32)(row * 128 + (qq & 7) * 16));
        uint4 vh = *(const uint4*)(g_znh + (size_t)(rowbase + row) * 64 + qq * 4);
        uint4 vl = *(const uint4*)(g_znl + (size_t)(rowbase + row) * 64 + qq * 4);
        *(uint4*)(smem + (sAh - sb) + off) = vh;
        *(uint4*)(smem + (sAl - sb) + off) = vl;
    }
    // ---- load B (weights) ----
    #pragma unroll
    for (int m = 0; m < 4; m++) {
        const int i2 = tid + 512 * m;
        const int n = i2 >> 4, qq = i2 & 15;
        const u32 off = (qq >> 3) * 16384 + sw128((u32)(n * 128 + (qq & 7) * 16));
        uint4 vh = *(const uint4*)(g_wth + m0 * 8192 + n * 64 + qq * 4);
        uint4 vl = *(const uint4*)(g_wtl + m0 * 8192 + n * 64 + qq * 4);
        *(uint4*)(smem + (sB0h - sb) + off) = vh;
        *(uint4*)(smem + (sB0l - sb) + off) = vl;
        if (job < 2) {
            vh = *(const uint4*)(g_wth + (m0 + 1) * 8192 + n * 64 + qq * 4);
            vl = *(const uint4*)(g_wtl + (m0 + 1) * 8192 + n * 64 + qq * 4);
            *(uint4*)(smem + (sB1h - sb) + off) = vh;
            *(uint4*)(smem + (sB1l - sb) + off) = vl;
        }
    }
    __syncthreads();
    if (tid < 128) msk[tid] = mask_val(mask, rowbase + tid, s_mi32);

    const int wm = (wid & 3) * 32;
    const int wn = (wid >> 2) * 32;
    const int a_row = (lane & 7) + ((lane >> 3) & 1) * 8;
    const int a_kb  = (lane >> 4) * 8;
    const int b_row = (lane & 7) + (lane >> 4) * 8;
    const int b_kb  = ((lane >> 3) & 1) * 8;

    float accL[2][4][4], accG[2][4][4];
    #pragma unroll
    for (int mi = 0; mi < 2; mi++)
        #pragma unroll
        for (int ni = 0; ni < 4; ni++)
            #pragma unroll
            for (int q = 0; q < 4; q++) { accL[mi][ni][q] = 0.f; accG[mi][ni][q] = 0.f; }

    #pragma unroll
    for (int kf = 0; kf < 8; kf++) {
        const u32 hoff = (kf >> 2) * 16384;
        const int kp = (kf & 3) * 16;
        u32 Ah[2][4], Al[2][4];
        #pragma unroll
        for (int mi = 0; mi < 2; mi++) {
            const u32 o = hoff + sw128((u32)((wm + mi * 16 + a_row) * 128 + (kp + a_kb) * 2));
            ldsm4(sAh + o, Ah[mi]);
            ldsm4(sAl + o, Al[mi]);
        }
        u32 Bh[2][4], Bl[2][4];
        #pragma unroll
        for (int nb = 0; nb < 2; nb++) {
            const u32 o = hoff + sw128((u32)((wn + nb * 16 + b_row) * 128 + (kp + b_kb) * 2));
            ldsm4(sB0h + o, Bh[nb]);
            ldsm4(sB0l + o, Bl[nb]);
        }
        #pragma unroll
        for (int mi = 0; mi < 2; mi++)
            #pragma unroll
            for (int ni = 0; ni < 4; ni++) {
                const u32* bh = Bh[ni >> 1] + (ni & 1) * 2;
                const u32* bl = Bl[ni >> 1] + (ni & 1) * 2;
                mma_bf16(accL[mi][ni], Ah[mi], bh);
                mma_bf16(accL[mi][ni], Ah[mi], bl);
                mma_bf16(accL[mi][ni], Al[mi], bh);
            }
        if (job < 2) {
            #pragma unroll
            for (int nb = 0; nb < 2; nb++) {
                const u32 o = hoff + sw128((u32)((wn + nb * 16 + b_row) * 128 + (kp + b_kb) * 2));
                ldsm4(sB1h + o, Bh[nb]);
                ldsm4(sB1l + o, Bl[nb]);
            }
            #pragma unroll
            for (int mi = 0; mi < 2; mi++)
                #pragma unroll
                for (int ni = 0; ni < 4; ni++) {
                    const u32* bh = Bh[ni >> 1] + (ni & 1) * 2;
                    const u32* bl = Bl[ni >> 1] + (ni & 1) * 2;
                    mma_bf16(accG[mi][ni], Ah[mi], bh);
                    mma_bf16(accG[mi][ni], Ah[mi], bl);
                    mma_bf16(accG[mi][ni], Al[mi], bh);
                }
        }
    }
    __syncthreads();

    if (job < 2) {
        const float* bl_ = job ? bb : ba;
        const float* bg_ = job ? bgb : bga;
        float* sT = (float*)(smem + 64 * 1024);   // [c][row], stride 132 (aliases B tiles)
        #pragma unroll
        for (int mi = 0; mi < 2; mi++) {
            const int r0 = wm + mi * 16 + (lane >> 2);
            const int r1 = r0 + 8;
            const float mv0 = msk[r0], mv1 = msk[r1];
            #pragma unroll
            for (int ni = 0; ni < 4; ni++) {
                const int c = wn + ni * 8 + (lane & 3) * 2;
                const float bl0 = __ldg(bl_ + c), bl1 = __ldg(bl_ + c + 1);
                const float bg0 = __ldg(bg_ + c), bg1 = __ldg(bg_ + c + 1);
                sT[c * 132 + r0]       = mv0 * sigm(accG[mi][ni][0] + bg0) * (accL[mi][ni][0] + bl0);
                sT[(c + 1) * 132 + r0] = mv0 * sigm(accG[mi][ni][1] + bg1) * (accL[mi][ni][1] + bl1);
                sT[c * 132 + r1]       = mv1 * sigm(accG[mi][ni][2] + bg0) * (accL[mi][ni][2] + bl0);
                sT[(c + 1) * 132 + r1] = mv1 * sigm(accG[mi][ni][3] + bg1) * (accL[mi][ni][3] + bl1);
            }
        }
        __syncthreads();
        u32* ph = job ? g_bh : g_ah;
        u32* pl = job ? g_bl : g_al;
        const int c = tid >> 2;
        const int rb = (tid & 3) * 32;
        #pragma unroll
        for (int j = 0; j < 8; j++) {
            float4 v = *(float4*)(sT + c * 132 + rb + j * 4);
            u32 h0, l0, h1, l1;
            split2(v.x, v.y, h0, l0);
            split2(v.z, v.w, h1, l1);
            const size_t p = (size_t)c * PLANE2 + (size_t)(rowbase + rb) / 2 + j * 2;
            *(uint2*)(ph + p) = make_uint2(h0, h1);
            *(uint2*)(pl + p) = make_uint2(l0, l1);
        }
    } else {
        #pragma unroll
        for (int mi = 0; mi < 2; mi++) {
            const int r0 = wm + mi * 16 + (lane >> 2);
            #pragma unroll
            for (int ni = 0; ni < 4; ni++) {
                const int c = wn + ni * 8 + (lane & 3) * 2;
                const float b0 = __ldg(bgo + c), b1 = __ldg(bgo + c + 1);
                *(float2*)(g_go + (size_t)(rowbase + r0) * C + c)
                    = make_float2(sigm(accL[mi][ni][0] + b0), sigm(accL[mi][ni][1] + b1));
                *(float2*)(g_go + (size_t)(rowbase + r0 + 8) * C + c)
                    = make_float2(sigm(accL[mi][ni][2] + b0), sigm(accL[mi][ni][3] + b1));
            }
        }
    }
}

// ============================================================================
// Kernel B: per-channel 512x512x512 NT GEMM via HMMA bf16 hi/lo 3-pass.
// cp.async 3-stage pipeline from bf16 planes. CTA = 128x128 tile of a channel.
// stage = Ahi|Alo|Bhi|Blo, each 128 rows x 128B (sw128) = 64KB.
// ============================================================================
#define KB_STAGE (64 * 1024)
#define KB_SMEM (3 * KB_STAGE)

__global__ __launch_bounds__(256, 1)
void kB()
{
    extern __shared__ __align__(1024) char smem[];
    const u32 sb = smem_u32(smem);
    const int tid = threadIdx.x;
    const int wid = tid >> 5, lane = tid & 31;
    const int i0 = (blockIdx.x & 3) * 128;
    const int j0 = (blockIdx.x >> 2) * 128;
    const size_t ch = blockIdx.y;
    const u32* base0 = g_ah + ch * PLANE2 + (size_t)i0 * 256;
    const u32* base1 = g_al + ch * PLANE2 + (size_t)i0 * 256;
    const u32* base2 = g_bh + ch * PLANE2 + (size_t)j0 * 256;
    const u32* base3 = g_bl + ch * PLANE2 + (size_t)j0 * 256;

    const int wm = (wid & 1) * 64;
    const int wn = (wid >> 1) * 32;
    const int a_row = (lane & 7) + ((lane >> 3) & 1) * 8;
    const int a_kb  = (lane >> 4) * 8;
    const int b_row = (lane & 7) + (lane >> 4) * 8;
    const int b_kb  = ((lane >> 3) & 1) * 8;

    float acc[4][4][4];
    #pragma unroll
    for (int mi = 0; mi < 4; mi++)
        #pragma unroll
        for (int ni = 0; ni < 4; ni++)
            #pragma unroll
            for (int q = 0; q < 4; q++) acc[mi][ni][q] = 0.0f;

    // per-thread fixed load slots: 16 cp.asyncs of 16B per chunk.
    // chunk = 64 k-elements = 32 u32 per row = 8 segments of 16B (4 u32).
    auto issue = [&](int ck) {
        const u32 st = sb + (ck % 3) * KB_STAGE;
        const u32 k0h = (u32)ck * 32;            // u32-pair offset of chunk
        #pragma unroll
        for (int m = 0; m < 16; m++) {
            const int id = tid + 256 * m;        // 0..4095
            const int tile = id >> 10;           // 0..3
            const int rem = id & 1023;
            const int row = rem >> 3, seg = rem & 7;
            const u32* src;
            if (tile == 0)      src = base0;
            else if (tile == 1) src = base1;
            else if (tile == 2) src = base2;
            else                src = base3;
            src += (size_t)row * 256 + k0h + seg * 4;   // FIXED: 16B = 4 u32
            const u32 dst = st + tile * 16384 + sw128((u32)(row * 128 + seg * 16));
            cpasync16(dst, src);
        }
        asm volatile("cp.async.commit_group;" ::: "memory");
    };

    issue(0);
    issue(1);

    #pragma unroll 1
    for (int ck = 0; ck < 8; ck++) {
        if (ck < 7) asm volatile("cp.async.wait_group 1;" ::: "memory");
        else        asm volatile("cp.async.wait_group 0;" ::: "memory");
        __syncthreads();
        const u32 st = sb + (ck % 3) * KB_STAGE;
        const u32 sAh = st, sAl = st + 16384, sBh = st + 32768, sBl = st + 49152;

        #pragma unroll
        for (int kf = 0; kf < 4; kf++) {
            u32 Ah[4][4], Al[4][4], Bh[2][4], Bl[2][4];
            #pragma unroll
            for (int mi = 0; mi < 4; mi++) {
                const u32 off = sw128((u32)((wm + mi * 16 + a_row) * 128 + (kf * 16 + a_kb) * 2));
                ldsm4(sAh + off, Ah[mi]);
                ldsm4(sAl + off, Al[mi]);
            }
            #pragma unroll
            for (int nb = 0; nb < 2; nb++) {
                const u32 off = sw128((u32)((wn + nb * 16 + b_row) * 128 + (kf * 16 + b_kb) * 2));
                ldsm4(sBh + off, Bh[nb]);
                ldsm4(sBl + off, Bl[nb]);
            }
            #pragma unroll
            for (int mi = 0; mi < 4; mi++)
                #pragma unroll
                for (int ni = 0; ni < 4; ni++) {
                    const u32* bh = Bh[ni >> 1] + (ni & 1) * 2;
                    const u32* bl = Bl[ni >> 1] + (ni & 1) * 2;
                    mma_bf16(acc[mi][ni], Ah[mi], bh);
                    mma_bf16(acc[mi][ni], Ah[mi], bl);
                    mma_bf16(acc[mi][ni], Al[mi], bh);
                }
        }
        __syncthreads();
        if (ck + 2 < 8) issue(ck + 2);
    }

    float* dst = g_kf + ch * PLANE;
    #pragma unroll
    for (int mi = 0; mi < 4; mi++) {
        const int rbase = i0 + wm + mi * 16 + (lane >> 2);
        #pragma unroll
        for (int ni = 0; ni < 4; ni++) {
            const int col = j0 + wn + ni * 8 + (lane & 3) * 2;
            *(float2*)(dst + (size_t)rbase * NN + col)
                = make_float2(acc[mi][ni][0], acc[mi][ni][1]);
            *(float2*)(dst + (size_t)(rbase + 8) * NN + col)
                = make_float2(acc[mi][ni][2], acc[mi][ni][3]);
        }
    }
}

// ============================================================================
// kPrepC: LN(k) over channels -> bf16 hi/lo planes g_knh/g_knl row-major.
// ============================================================================
__global__ __launch_bounds__(256)
void kPrepC(const float* __restrict__ go_, const float* __restrict__ bo_)
{
    __shared__ float kn[32 * 129];
    const int tid = threadIdx.x;
    const int rowbase = blockIdx.x * 32;

    { // gather: [c][row] planes -> smem [row][c]
        const int row = tid & 31;
        #pragma unroll
        for (int m = 0; m < 16; m++) {
            const int c = (tid >> 5) + m * 8;
            kn[row * 129 + c] = g_kf[(size_t)c * PLANE + rowbase + row];
        }
    }
    __syncthreads();
    { // LN per row
        const int w = tid >> 5, lane = tid & 31;
        #pragma unroll
        for (int rr = 0; rr < 4; rr++) {
            const int r = 4 * w + rr;
            float x[4];
            #pragma unroll
            for (int m = 0; m < 4; m++) x[m] = kn[r * 129 + lane + 32 * m];
            float s = x[0] + x[1] + x[2] + x[3];
            float q = x[0]*x[0] + x[1]*x[1] + x[2]*x[2] + x[3]*x[3];
            #pragma unroll
            for (int o = 16; o; o >>= 1) {
                s += __shfl_xor_sync(~0u, s, o);
                q += __shfl_xor_sync(~0u, q, o);
            }
            const float mean = s * (1.0f / C);
            const float rstd = rsqrtf(q * (1.0f / C) - mean * mean + 1e-5f);
            #pragma unroll
            for (int m = 0; m < 4; m++) {
                const int c = lane + 32 * m;
                kn[r * 129 + c] = (x[m] - mean) * rstd * go_[c] + bo_[c];
            }
        }
    }
    __syncthreads();
    { // pack to bf16 hi/lo pairs
        const int row = tid >> 3, j = tid & 7;
        #pragma unroll
        for (int t = 0; t < 8; t++) {
            const int p = j * 8 + t;
            u32 h, l;
            split2(kn[row * 129 + 2 * p], kn[row * 129 + 2 * p + 1], h, l);
            g_knh[(size_t)(rowbase + row) * 64 + p] = h;
            g_knl[(size_t)(rowbase + row) * 64 + p] = l;
        }
    }
}

// ============================================================================
// kProjC: out = go * (LN(k) @ Wo + bo). HMMA, grid 2048, 512 threads.
// ============================================================================
#define PJC_SMEM (128 * 1024)
__global__ __launch_bounds__(512, 1)
void kProjC(const float* __restrict__ bo, float* __restrict__ out)
{
    extern __shared__ __align__(1024) char smem[];
    const u32 sb = smem_u32(smem);
    const u32 sAh = sb,            sAl = sb + 32*1024;
    const u32 sBh = sb + 64*1024,  sBl = sb + 96*1024;
    const int tid = threadIdx.x;
    const int wid = tid >> 5, lane = tid & 31;
    const int rowbase = blockIdx.x * 128;

    #pragma unroll
    for (int m = 0; m < 4; m++) {
        const int id = tid + 512 * m;
        const int row = id >> 4, qq = id & 15;
        const u32 off = (qq >> 3) * 16384 + sw128((u32)(row * 128 + (qq & 7) * 16));
        uint4 vh = *(const uint4*)(g_knh + (size_t)(rowbase + row) * 64 + qq * 4);
        uint4 vl = *(const uint4*)(g_knl + (size_t)(rowbase + row) * 64 + qq * 4);
        *(uint4*)(smem + (sAh - sb) + off) = vh;
        *(uint4*)(smem + (sAl - sb) + off) = vl;
    }
    #pragma unroll
    for (int m = 0; m < 4; m++) {
        const int i2 = tid + 512 * m;
        const int n = i2 >> 4, qq = i2 & 15;
        const u32 off = (qq >> 3) * 16384 + sw128((u32)(n * 128 + (qq & 7) * 16));
        uint4 vh = *(const uint4*)(g_wth + 5 * 8192 + n * 64 + qq * 4);
        uint4 vl = *(const uint4*)(g_wtl + 5 * 8192 + n * 64 + qq * 4);
        *(uint4*)(smem + (sBh - sb) + off) = vh;
        *(uint4*)(smem + (sBl - sb) + off) = vl;
    }
    __syncthreads();

    const int wm = (wid & 3) * 32;
    const int wn = (wid >> 2) * 32;
    const int a_row = (lane & 7) + ((lane >> 3) & 1) * 8;
    const int a_kb  = (lane >> 4) * 8;
    const int b_row = (lane & 7) + (lane >> 4) * 8;
    const int b_kb  = ((lane >> 3) & 1) * 8;

    float accL[2][4][4];
    #pragma unroll
    for (int mi = 0; mi < 2; mi++)
        #pragma unroll
        for (int ni = 0; ni < 4; ni++)
            #pragma unroll
            for (int q = 0; q < 4; q++) accL[mi][ni][q] = 0.f;

    #pragma unroll
    for (int kf = 0; kf < 8; kf++) {
        const u32 hoff = (kf >> 2) * 16384;
        const int kp = (kf & 3) * 16;
        u32 Ah[2][4], Al[2][4], Bh[2][4], Bl[2][4];
        #pragma unroll
        for (int mi = 0; mi < 2; mi++) {
            const u32 o = hoff + sw128((u32)((wm + mi * 16 + a_row) * 128 + (kp + a_kb) * 2));
            ldsm4(sAh + o, Ah[mi]);
            ldsm4(sAl + o, Al[mi]);
        }
        #pragma unroll
        for (int nb = 0; nb < 2; nb++) {
            const u32 o = hoff + sw128((u32)((wn + nb * 16 + b_row) * 128 + (kp + b_kb) * 2));
            ldsm4(sBh + o, Bh[nb]);
            ldsm4(sBl + o, Bl[nb]);
        }
        #pragma unroll
        for (int mi = 0; mi < 2; mi++)
            #pragma unroll
            for (int ni = 0; ni < 4; ni++) {
                const u32* bh = Bh[ni >> 1] + (ni & 1) * 2;
                const u32* bl = Bl[ni >> 1] + (ni & 1) * 2;
                mma_bf16(accL[mi][ni], Ah[mi], bh);
                mma_bf16(accL[mi][ni], Ah[mi], bl);
                mma_bf16(accL[mi][ni], Al[mi], bh);
            }
    }

    #pragma unroll
    for (int mi = 0; mi < 2; mi++) {
        const int r0 = wm + mi * 16 + (lane >> 2);
        #pragma unroll
        for (int ni = 0; ni < 4; ni++) {
            const int c = wn + ni * 8 + (lane & 3) * 2;
            const float b0 = __ldg(bo + c), b1 = __ldg(bo + c + 1);
            const size_t ro0 = (size_t)(rowbase + r0) * C + c;
            const size_t ro1 = (size_t)(rowbase + r0 + 8) * C + c;
            const float2 gg0 = *(const float2*)(g_go + ro0);
            const float2 gg1 = *(const float2*)(g_go + ro1);
            *(float2*)(out + ro0)
                = make_float2(gg0.x * (accL[mi][ni][0] + b0), gg0.y * (accL[mi][ni][1] + b1));
            *(float2*)(out + ro1)
                = make_float2(gg1.x * (accL[mi][ni][2] + b0), gg1.y * (accL[mi][ni][3] + b1));
        }
    }
}

// ============================================================================
extern "C" void kernel_launch(void* const* d_in, const int* in_sizes, int n_in,
                              void* d_out, int out_size)
{
    const float*         z    = (const float*)d_in[0];
    const unsigned char* mask = (const unsigned char*)d_in[1];
    const float* gin = (const float*)d_in[2],  *bin = (const float*)d_in[3];
    const float* Wa  = (const float*)d_in[4],  *ba  = (const float*)d_in[5];
    const float* Wga = (const float*)d_in[6],  *bga = (const float*)d_in[7];
    const float* Wb  = (const float*)d_in[8],  *bb  = (const float*)d_in[9];
    const float* Wgb = (const float*)d_in[10], *bgb = (const float*)d_in[11];
    const float* g_o = (const float*)d_in[12], *b_o = (const float*)d_in[13];
    const float* Wgo = (const float*)d_in[14], *bgo = (const float*)d_in[15];
    const float* Wo  = (const float*)d_in[16], *bo  = (const float*)d_in[17];
    float* out = (float*)d_out;

    static int attr_set = 0;
    if (!attr_set) {
        cudaFuncSetAttribute(kB, cudaFuncAttributeMaxDynamicSharedMemorySize, KB_SMEM);
        cudaFuncSetAttribute(kProj, cudaFuncAttributeMaxDynamicSharedMemorySize, PJ_SMEM);
        cudaFuncSetAttribute(kProjC, cudaFuncAttributeMaxDynamicSharedMemorySize, PJC_SMEM);
        attr_set = 1;
    }

    kW<<<6, 256>>>(Wa, Wga, Wb, Wgb, Wgo, Wo);
    kPrep<<<NROWS / 32, 256>>>(z, gin, bin);
    kProj<<<dim3(2048, 3), 512, PJ_SMEM>>>(mask, ba, bga, bb, bgb, bgo);
    kB<<<dim3(16, C), 256, KB_SMEM>>>();
    kPrepC<<<NROWS / 32, 256>>>(g_o, b_o);
    kProjC<<<2048, 512, PJC_SMEM>>>(bo, out);
}

// round 9
// speedup vs baseline: 2.5311x; 1.1023x over previous
#include <cuda_runtime.h>

typedef unsigned long long u64;
typedef unsigned int u32;

#define NN 512
#define C 128
#define NROWS (NN * NN)
#define PLANE ((size_t)NROWS)
#define PLANE2 ((size_t)(NROWS / 2))   // u32-pair plane size

// ---- scratch ----
__device__ u32  g_wth[6 * 128 * 64];         // W^T hi bf16 pairs [mat][n][64]
__device__ u32  g_wtl[6 * 128 * 64];
__device__ u32  g_ah[(size_t)C * PLANE2];    // a planes bf16 pairs [c][flat/2]
__device__ u32  g_al[(size_t)C * PLANE2];
__device__ u32  g_bh[(size_t)C * PLANE2];
__device__ u32  g_bl[(size_t)C * PLANE2];
__device__ float g_go[(size_t)NROWS * C];    // gate, [row][c]
__device__ float g_kf[(size_t)C * NROWS];    // einsum out fp32 [c][i*512+j]

// ---- helpers ----
__device__ __forceinline__ float sigm(float x) { return 1.0f / (1.0f + __expf(-x)); }
__device__ __forceinline__ u32 bf16x2(float hi_val, float lo_val) {
    u32 r; asm("cvt.rn.bf16x2.f32 %0, %1, %2;" : "=r"(r) : "f"(hi_val), "f"(lo_val)); return r;
}
__device__ __forceinline__ u32 smem_u32(const void* p) {
    u32 a; asm("{ .reg .u64 t; cvta.to.shared.u64 t, %1; cvt.u32.u64 %0, t; }" : "=r"(a) : "l"(p));
    return a;
}
__device__ __forceinline__ u32 sw128(u32 x) { return x ^ ((x >> 3) & 0x70); }

__device__ __forceinline__ void ldsm4(u32 addr, u32* r) {
    asm volatile("ldmatrix.sync.aligned.m8n8.x4.shared.b16 {%0,%1,%2,%3}, [%4];"
        : "=r"(r[0]), "=r"(r[1]), "=r"(r[2]), "=r"(r[3]) : "r"(addr));
}
__device__ __forceinline__ void mma_bf16(float* c, const u32* a, const u32* b) {
    asm volatile("mma.sync.aligned.m16n8k16.row.col.f32.bf16.bf16.f32 "
        "{%0,%1,%2,%3}, {%4,%5,%6,%7}, {%8,%9}, {%0,%1,%2,%3};"
        : "+f"(c[0]), "+f"(c[1]), "+f"(c[2]), "+f"(c[3])
        : "r"(a[0]), "r"(a[1]), "r"(a[2]), "r"(a[3]), "r"(b[0]), "r"(b[1]));
}
__device__ __forceinline__ void cpasync16(u32 dst, const void* src) {
    asm volatile("cp.async.cg.shared.global [%0], [%1], 16;" :: "r"(dst), "l"(src));
}

__device__ __forceinline__ int detect_mask_is_int32(const unsigned char* m) {
    const uint4* p = (const uint4*)m;
    unsigned acc = 0;
    #pragma unroll
    for (int i = 0; i < 4; i++) { uint4 v = p[i]; acc |= v.x | v.y | v.z | v.w; }
    return (acc & 0xFFFFFF00u) == 0u;
}
__device__ __forceinline__ float mask_val(const unsigned char* m, int row, int i32) {
    int v = i32 ? ((const int*)m)[row] : (int)m[row];
    return v ? 0.0f : 1.0f;
}

__device__ __forceinline__ void split2(float v0, float v1, u32& h, u32& l) {
    h = bf16x2(v1, v0);
    const float h0 = __uint_as_float(h << 16);
    const float h1 = __uint_as_float(h & 0xFFFF0000u);
    l = bf16x2(v1 - h1, v0 - h0);
}

// ============================================================================
// kW: transpose 6 weight matrices [k][n] -> bf16 hi/lo [mat][n][k]. grid=6.
// ============================================================================
__global__ __launch_bounds__(256)
void kW(const float* __restrict__ Wa, const float* __restrict__ Wga,
        const float* __restrict__ Wb, const float* __restrict__ Wgb,
        const float* __restrict__ Wgo, const float* __restrict__ Wo)
{
    const float* Ws[6] = {Wa, Wga, Wb, Wgb, Wgo, Wo};
    const float* W = Ws[blockIdx.x];
    for (int idx = threadIdx.x; idx < 128 * 64; idx += 256) {
        const int n = idx >> 6, k2 = idx & 63;
        u32 h, l;
        split2(W[(2 * k2) * 128 + n], W[(2 * k2 + 1) * 128 + n], h, l);
        g_wth[blockIdx.x * 8192 + n * 64 + k2] = h;
        g_wtl[blockIdx.x * 8192 + n * 64 + k2] = l;
    }
}

// ============================================================================
// kProjA: fused LN(z) + all 5 projections. grid=2048, 512 threads.
// smem: sA hi/lo (64KB @0) | wbuf0 (64KB @64K) | wbuf1 (64KB @128K);
// epilogue sT (67.6KB) aliases wbuf region (free at that time).
// ============================================================================
#define PJ_SMEM (192 * 1024)
__global__ __launch_bounds__(512, 1)
void kProjA(const float* __restrict__ z, const unsigned char* __restrict__ mask,
            const float* __restrict__ gin, const float* __restrict__ bin,
            const float* __restrict__ ba,  const float* __restrict__ bga,
            const float* __restrict__ bb,  const float* __restrict__ bgb,
            const float* __restrict__ bgo)
{
    extern __shared__ __align__(1024) char smem[];
    __shared__ float msk[128];
    __shared__ int s_mi32;
    const u32 sb = smem_u32(smem);
    const int tid = threadIdx.x;
    const int wid = tid >> 5, lane = tid & 31;
    const int rowbase = blockIdx.x * 128;

    // weight prefetch into 64KB buffer (hi 32KB + lo 32KB, 2x16KB halves each)
    auto wload = [&](int mat, u32 boff) {
        #pragma unroll
        for (int s = 0; s < 8; s++) {
            const int id = tid + 512 * s;     // 0..4095
            const int hilo = id >> 11;
            const int rem = id & 2047;
            const int n = rem >> 4, qq = rem & 15;
            const u32 dst = sb + boff + hilo * 32768
                          + (qq >> 3) * 16384 + sw128((u32)(n * 128 + (qq & 7) * 16));
            const u32* src = (hilo ? g_wtl : g_wth) + mat * 8192 + n * 64 + qq * 4;
            cpasync16(dst, src);
        }
        asm volatile("cp.async.commit_group;" ::: "memory");
    };

    if (tid == 0) s_mi32 = detect_mask_is_int32(mask);
    wload(0, 65536);    // Wa  -> b0
    wload(1, 131072);   // Wga -> b1

    // ---- LN(z) in registers -> sA bf16 hi/lo swizzled ----
    {
        const int lrow = tid >> 2, q = tid & 3;
        float v[32];
        const float* zr = z + (size_t)(rowbase + lrow) * C + q * 32;
        #pragma unroll
        for (int i = 0; i < 8; i++) *(float4*)(v + i * 4) = *(const float4*)(zr + i * 4);
        float s = 0.f, qsum = 0.f;
        #pragma unroll
        for (int i = 0; i < 32; i++) { s += v[i]; qsum += v[i] * v[i]; }
        s += __shfl_xor_sync(~0u, s, 1);  s += __shfl_xor_sync(~0u, s, 2);
        qsum += __shfl_xor_sync(~0u, qsum, 1);  qsum += __shfl_xor_sync(~0u, qsum, 2);
        const float mean = s * (1.0f / C);
        const float rstd = rsqrtf(qsum * (1.0f / C) - mean * mean + 1e-5f);
        #pragma unroll
        for (int i = 0; i < 16; i++) {
            const int c0 = q * 32 + 2 * i;
            const float x0 = (v[2*i]   - mean) * rstd * __ldg(gin + c0)     + __ldg(bin + c0);
            const float x1 = (v[2*i+1] - mean) * rstd * __ldg(gin + c0 + 1) + __ldg(bin + c0 + 1);
            u32 h, l; split2(x0, x1, h, l);
            const u32 off = (q >> 1) * 16384 + sw128((u32)(lrow * 128 + ((q & 1) * 16 + i) * 4));
            *(u32*)(smem + off) = h;
            *(u32*)(smem + 32768 + off) = l;
        }
    }
    __syncthreads();
    if (tid < 128) msk[tid] = mask_val(mask, rowbase + tid, s_mi32);

    const u32 sAh = sb, sAl = sb + 32768;
    const int wm = (wid & 3) * 32;
    const int wn = (wid >> 2) * 32;
    const int a_row = (lane & 7) + ((lane >> 3) & 1) * 8;
    const int a_kb  = (lane >> 4) * 8;
    const int b_row = (lane & 7) + (lane >> 4) * 8;
    const int b_kb  = ((lane >> 3) & 1) * 8;

    float accL[2][4][4], accG[2][4][4];

    // ---- phases 0 (a: Wa/Wga) and 1 (b: Wb/Wgb) ----
    #pragma unroll 1
    for (int t = 0; t < 2; t++) {
        asm volatile("cp.async.wait_group 0;" ::: "memory");
        __syncthreads();
        #pragma unroll
        for (int mi = 0; mi < 2; mi++)
            #pragma unroll
            for (int ni = 0; ni < 4; ni++)
                #pragma unroll
                for (int qk = 0; qk < 4; qk++) { accL[mi][ni][qk] = 0.f; accG[mi][ni][qk] = 0.f; }

        const u32 sB0h = sb + 65536,  sB0l = sb + 65536 + 32768;   // linear
        const u32 sB1h = sb + 131072, sB1l = sb + 131072 + 32768;  // gate
        #pragma unroll
        for (int kf = 0; kf < 8; kf++) {
            const u32 hoff = (kf >> 2) * 16384;
            const int kp = (kf & 3) * 16;
            u32 Ah[2][4], Al[2][4], Bh[2][4], Bl[2][4];
            #pragma unroll
            for (int mi = 0; mi < 2; mi++) {
                const u32 o = hoff + sw128((u32)((wm + mi * 16 + a_row) * 128 + (kp + a_kb) * 2));
                ldsm4(sAh + o, Ah[mi]);
                ldsm4(sAl + o, Al[mi]);
            }
            #pragma unroll
            for (int nb = 0; nb < 2; nb++) {
                const u32 o = hoff + sw128((u32)((wn + nb * 16 + b_row) * 128 + (kp + b_kb) * 2));
                ldsm4(sB0h + o, Bh[nb]);
                ldsm4(sB0l + o, Bl[nb]);
            }
            #pragma unroll
            for (int mi = 0; mi < 2; mi++)
                #pragma unroll
                for (int ni = 0; ni < 4; ni++) {
                    const u32* bh = Bh[ni >> 1] + (ni & 1) * 2;
                    const u32* bl = Bl[ni >> 1] + (ni & 1) * 2;
                    mma_bf16(accL[mi][ni], Ah[mi], bh);
                    mma_bf16(accL[mi][ni], Ah[mi], bl);
                    mma_bf16(accL[mi][ni], Al[mi], bh);
                }
            #pragma unroll
            for (int nb = 0; nb < 2; nb++) {
                const u32 o = hoff + sw128((u32)((wn + nb * 16 + b_row) * 128 + (kp + b_kb) * 2));
                ldsm4(sB1h + o, Bh[nb]);
                ldsm4(sB1l + o, Bl[nb]);
            }
            #pragma unroll
            for (int mi = 0; mi < 2; mi++)
                #pragma unroll
                for (int ni = 0; ni < 4; ni++) {
                    const u32* bh = Bh[ni >> 1] + (ni & 1) * 2;
                    const u32* bl = Bl[ni >> 1] + (ni & 1) * 2;
                    mma_bf16(accG[mi][ni], Ah[mi], bh);
                    mma_bf16(accG[mi][ni], Ah[mi], bl);
                    mma_bf16(accG[mi][ni], Al[mi], bh);
                }
        }
        __syncthreads();

        // epilogue: gate + mask, transpose via sT, store bf16 planes
        {
            const float* bl_ = t ? bb : ba;
            const float* bg_ = t ? bgb : bga;
            float* sT = (float*)(smem + 65536);   // [c][row], stride 132
            #pragma unroll
            for (int mi = 0; mi < 2; mi++) {
                const int r0 = wm + mi * 16 + (lane >> 2);
                const int r1 = r0 + 8;
                const float mv0 = msk[r0], mv1 = msk[r1];
                #pragma unroll
                for (int ni = 0; ni < 4; ni++) {
                    const int c = wn + ni * 8 + (lane & 3) * 2;
                    const float bl0 = __ldg(bl_ + c), bl1 = __ldg(bl_ + c + 1);
                    const float bg0 = __ldg(bg_ + c), bg1 = __ldg(bg_ + c + 1);
                    sT[c * 132 + r0]       = mv0 * sigm(accG[mi][ni][0] + bg0) * (accL[mi][ni][0] + bl0);
                    sT[(c + 1) * 132 + r0] = mv0 * sigm(accG[mi][ni][1] + bg1) * (accL[mi][ni][1] + bl1);
                    sT[c * 132 + r1]       = mv1 * sigm(accG[mi][ni][2] + bg0) * (accL[mi][ni][2] + bl0);
                    sT[(c + 1) * 132 + r1] = mv1 * sigm(accG[mi][ni][3] + bg1) * (accL[mi][ni][3] + bl1);
                }
            }
            __syncthreads();
            u32* ph = t ? g_bh : g_ah;
            u32* pl = t ? g_bl : g_al;
            const int c = tid >> 2;
            const int rb = (tid & 3) * 32;
            #pragma unroll
            for (int j = 0; j < 8; j++) {
                float4 vv = *(float4*)(sT + c * 132 + rb + j * 4);
                u32 h0, l0, h1, l1;
                split2(vv.x, vv.y, h0, l0);
                split2(vv.z, vv.w, h1, l1);
                const size_t p = (size_t)c * PLANE2 + (size_t)(rowbase + rb) / 2 + j * 2;
                *(uint2*)(ph + p) = make_uint2(h0, h1);
                *(uint2*)(pl + p) = make_uint2(l0, l1);
            }
        }
        __syncthreads();

        // prefetch next phase weights
        if (t == 0) { wload(2, 65536); wload(3, 131072); }
        else        { wload(4, 65536); }
    }

    // ---- phase go: Wgo ----
    asm volatile("cp.async.wait_group 0;" ::: "memory");
    __syncthreads();
    #pragma unroll
    for (int mi = 0; mi < 2; mi++)
        #pragma unroll
        for (int ni = 0; ni < 4; ni++)
            #pragma unroll
            for (int qk = 0; qk < 4; qk++) accL[mi][ni][qk] = 0.f;
    {
        const u32 sBh = sb + 65536, sBl = sb + 65536 + 32768;
        #pragma unroll
        for (int kf = 0; kf < 8; kf++) {
            const u32 hoff = (kf >> 2) * 16384;
            const int kp = (kf & 3) * 16;
            u32 Ah[2][4], Al[2][4], Bh[2][4], Bl[2][4];
            #pragma unroll
            for (int mi = 0; mi < 2; mi++) {
                const u32 o = hoff + sw128((u32)((wm + mi * 16 + a_row) * 128 + (kp + a_kb) * 2));
                ldsm4(sAh + o, Ah[mi]);
                ldsm4(sAl + o, Al[mi]);
            }
            #pragma unroll
            for (int nb = 0; nb < 2; nb++) {
                const u32 o = hoff + sw128((u32)((wn + nb * 16 + b_row) * 128 + (kp + b_kb) * 2));
                ldsm4(sBh + o, Bh[nb]);
                ldsm4(sBl + o, Bl[nb]);
            }
            #pragma unroll
            for (int mi = 0; mi < 2; mi++)
                #pragma unroll
                for (int ni = 0; ni < 4; ni++) {
                    const u32* bh = Bh[ni >> 1] + (ni & 1) * 2;
                    const u32* bl = Bl[ni >> 1] + (ni & 1) * 2;
                    mma_bf16(accL[mi][ni], Ah[mi], bh);
                    mma_bf16(accL[mi][ni], Ah[mi], bl);
                    mma_bf16(accL[mi][ni], Al[mi], bh);
                }
        }
    }
    #pragma unroll
    for (int mi = 0; mi < 2; mi++) {
        const int r0 = wm + mi * 16 + (lane >> 2);
        #pragma unroll
        for (int ni = 0; ni < 4; ni++) {
            const int c = wn + ni * 8 + (lane & 3) * 2;
            const float b0 = __ldg(bgo + c), b1 = __ldg(bgo + c + 1);
            *(float2*)(g_go + (size_t)(rowbase + r0) * C + c)
                = make_float2(sigm(accL[mi][ni][0] + b0), sigm(accL[mi][ni][1] + b1));
            *(float2*)(g_go + (size_t)(rowbase + r0 + 8) * C + c)
                = make_float2(sigm(accL[mi][ni][2] + b0), sigm(accL[mi][ni][3] + b1));
        }
    }
}

// ============================================================================
// Kernel B: per-channel 512x512x512 NT GEMM via HMMA bf16 hi/lo 3-pass.
// (unchanged from round 8 — known good)
// ============================================================================
#define KB_STAGE (64 * 1024)
#define KB_SMEM (3 * KB_STAGE)

__global__ __launch_bounds__(256, 1)
void kB()
{
    extern __shared__ __align__(1024) char smem[];
    const u32 sb = smem_u32(smem);
    const int tid = threadIdx.x;
    const int wid = tid >> 5, lane = tid & 31;
    const int i0 = (blockIdx.x & 3) * 128;
    const int j0 = (blockIdx.x >> 2) * 128;
    const size_t ch = blockIdx.y;
    const u32* base0 = g_ah + ch * PLANE2 + (size_t)i0 * 256;
    const u32* base1 = g_al + ch * PLANE2 + (size_t)i0 * 256;
    const u32* base2 = g_bh + ch * PLANE2 + (size_t)j0 * 256;
    const u32* base3 = g_bl + ch * PLANE2 + (size_t)j0 * 256;

    const int wm = (wid & 1) * 64;
    const int wn = (wid >> 1) * 32;
    const int a_row = (lane & 7) + ((lane >> 3) & 1) * 8;
    const int a_kb  = (lane >> 4) * 8;
    const int b_row = (lane & 7) + (lane >> 4) * 8;
    const int b_kb  = ((lane >> 3) & 1) * 8;

    float acc[4][4][4];
    #pragma unroll
    for (int mi = 0; mi < 4; mi++)
        #pragma unroll
        for (int ni = 0; ni < 4; ni++)
            #pragma unroll
            for (int q = 0; q < 4; q++) acc[mi][ni][q] = 0.0f;

    auto issue = [&](int ck) {
        const u32 st = sb + (ck % 3) * KB_STAGE;
        const u32 k0h = (u32)ck * 32;
        #pragma unroll
        for (int m = 0; m < 16; m++) {
            const int id = tid + 256 * m;
            const int tile = id >> 10;
            const int rem = id & 1023;
            const int row = rem >> 3, seg = rem & 7;
            const u32* src;
            if (tile == 0)      src = base0;
            else if (tile == 1) src = base1;
            else if (tile == 2) src = base2;
            else                src = base3;
            src += (size_t)row * 256 + k0h + seg * 4;
            const u32 dst = st + tile * 16384 + sw128((u32)(row * 128 + seg * 16));
            cpasync16(dst, src);
        }
        asm volatile("cp.async.commit_group;" ::: "memory");
    };

    issue(0);
    issue(1);

    #pragma unroll 1
    for (int ck = 0; ck < 8; ck++) {
        if (ck < 7) asm volatile("cp.async.wait_group 1;" ::: "memory");
        else        asm volatile("cp.async.wait_group 0;" ::: "memory");
        __syncthreads();
        const u32 st = sb + (ck % 3) * KB_STAGE;
        const u32 sAh = st, sAl = st + 16384, sBh = st + 32768, sBl = st + 49152;

        #pragma unroll
        for (int kf = 0; kf < 4; kf++) {
            u32 Ah[4][4], Al[4][4], Bh[2][4], Bl[2][4];
            #pragma unroll
            for (int mi = 0; mi < 4; mi++) {
                const u32 off = sw128((u32)((wm + mi * 16 + a_row) * 128 + (kf * 16 + a_kb) * 2));
                ldsm4(sAh + off, Ah[mi]);
                ldsm4(sAl + off, Al[mi]);
            }
            #pragma unroll
            for (int nb = 0; nb < 2; nb++) {
                const u32 off = sw128((u32)((wn + nb * 16 + b_row) * 128 + (kf * 16 + b_kb) * 2));
                ldsm4(sBh + off, Bh[nb]);
                ldsm4(sBl + off, Bl[nb]);
            }
            #pragma unroll
            for (int mi = 0; mi < 4; mi++)
                #pragma unroll
                for (int ni = 0; ni < 4; ni++) {
                    const u32* bh = Bh[ni >> 1] + (ni & 1) * 2;
                    const u32* bl = Bl[ni >> 1] + (ni & 1) * 2;
                    mma_bf16(acc[mi][ni], Ah[mi], bh);
                    mma_bf16(acc[mi][ni], Ah[mi], bl);
                    mma_bf16(acc[mi][ni], Al[mi], bh);
                }
        }
        __syncthreads();
        if (ck + 2 < 8) issue(ck + 2);
    }

    float* dst = g_kf + ch * PLANE;
    #pragma unroll
    for (int mi = 0; mi < 4; mi++) {
        const int rbase = i0 + wm + mi * 16 + (lane >> 2);
        #pragma unroll
        for (int ni = 0; ni < 4; ni++) {
            const int col = j0 + wn + ni * 8 + (lane & 3) * 2;
            *(float2*)(dst + (size_t)rbase * NN + col)
                = make_float2(acc[mi][ni][0], acc[mi][ni][1]);
            *(float2*)(dst + (size_t)(rbase + 8) * NN + col)
                = make_float2(acc[mi][ni][2], acc[mi][ni][3]);
        }
    }
}

// ============================================================================
// kOut: fused LN(k) + (@Wo + bo) * go -> out. grid=2048, 512 threads.
// smem: kn [128][129] f32 (66048B @0) | sA hi/lo (64KB @66048) | wbuf (64KB @131584)
// ============================================================================
#define KO_KN 66048
#define KO_A  66048
#define KO_W  131584
#define KO_SMEM (KO_W + 65536)
__global__ __launch_bounds__(512, 1)
void kOut(const float* __restrict__ go_, const float* __restrict__ bo_,
          const float* __restrict__ bo, float* __restrict__ out)
{
    extern __shared__ __align__(1024) char smem[];
    const u32 sb = smem_u32(smem);
    const int tid = threadIdx.x;
    const int wid = tid >> 5, lane = tid & 31;
    const int rowbase = blockIdx.x * 128;
    float* kn = (float*)smem;   // [row][c], stride 129

    // prefetch Wo (mat 5) into wbuf
    #pragma unroll
    for (int s = 0; s < 8; s++) {
        const int id = tid + 512 * s;
        const int hilo = id >> 11;
        const int rem = id & 2047;
        const int n = rem >> 4, qq = rem & 15;
        const u32 dst = sb + KO_W + hilo * 32768
                      + (qq >> 3) * 16384 + sw128((u32)(n * 128 + (qq & 7) * 16));
        const u32* src = (hilo ? g_wtl : g_wth) + 5 * 8192 + n * 64 + qq * 4;
        cpasync16(dst, src);
    }
    asm volatile("cp.async.commit_group;" ::: "memory");

    // stage g_kf -> kn[row][c]
    #pragma unroll
    for (int s = 0; s < 8; s++) {
        const int id = tid + 512 * s;        // 0..4095
        const int c = id >> 5, rf = id & 31;
        float4 vv = *(const float4*)(g_kf + (size_t)c * PLANE + rowbase + rf * 4);
        kn[(rf * 4 + 0) * 129 + c] = vv.x;
        kn[(rf * 4 + 1) * 129 + c] = vv.y;
        kn[(rf * 4 + 2) * 129 + c] = vv.z;
        kn[(rf * 4 + 3) * 129 + c] = vv.w;
    }
    __syncthreads();

    // LN in registers -> sA bf16 hi/lo
    {
        const int lrow = tid >> 2, q = tid & 3;
        float v[32];
        #pragma unroll
        for (int i = 0; i < 32; i++) v[i] = kn[lrow * 129 + q * 32 + i];
        float s = 0.f, qsum = 0.f;
        #pragma unroll
        for (int i = 0; i < 32; i++) { s += v[i]; qsum += v[i] * v[i]; }
        s += __shfl_xor_sync(~0u, s, 1);  s += __shfl_xor_sync(~0u, s, 2);
        qsum += __shfl_xor_sync(~0u, qsum, 1);  qsum += __shfl_xor_sync(~0u, qsum, 2);
        const float mean = s * (1.0f / C);
        const float rstd = rsqrtf(qsum * (1.0f / C) - mean * mean + 1e-5f);
        __syncthreads();   // kn reads done before sA overwrites nothing (separate region) — kept for safety
        #pragma unroll
        for (int i = 0; i < 16; i++) {
            const int c0 = q * 32 + 2 * i;
            const float x0 = (v[2*i]   - mean) * rstd * __ldg(go_ + c0)     + __ldg(bo_ + c0);
            const float x1 = (v[2*i+1] - mean) * rstd * __ldg(go_ + c0 + 1) + __ldg(bo_ + c0 + 1);
            u32 h, l; split2(x0, x1, h, l);
            const u32 off = KO_A + (q >> 1) * 16384
                          + sw128((u32)(lrow * 128 + ((q & 1) * 16 + i) * 4));
            *(u32*)(smem + off) = h;
            *(u32*)(smem + 32768 + off) = l;
        }
    }
    __syncthreads();
    asm volatile("cp.async.wait_group 0;" ::: "memory");
    __syncthreads();

    const u32 sAh = sb + KO_A, sAl = sb + KO_A + 32768;
    const u32 sBh = sb + KO_W, sBl = sb + KO_W + 32768;
    const int wm = (wid & 3) * 32;
    const int wn = (wid >> 2) * 32;
    const int a_row = (lane & 7) + ((lane >> 3) & 1) * 8;
    const int a_kb  = (lane >> 4) * 8;
    const int b_row = (lane & 7) + (lane >> 4) * 8;
    const int b_kb  = ((lane >> 3) & 1) * 8;

    float accL[2][4][4];
    #pragma unroll
    for (int mi = 0; mi < 2; mi++)
        #pragma unroll
        for (int ni = 0; ni < 4; ni++)
            #pragma unroll
            for (int qk = 0; qk < 4; qk++) accL[mi][ni][qk] = 0.f;

    #pragma unroll
    for (int kf = 0; kf < 8; kf++) {
        const u32 hoff = (kf >> 2) * 16384;
        const int kp = (kf & 3) * 16;
        u32 Ah[2][4], Al[2][4], Bh[2][4], Bl[2][4];
        #pragma unroll
        for (int mi = 0; mi < 2; mi++) {
            const u32 o = hoff + sw128((u32)((wm + mi * 16 + a_row) * 128 + (kp + a_kb) * 2));
            ldsm4(sAh + o, Ah[mi]);
            ldsm4(sAl + o, Al[mi]);
        }
        #pragma unroll
        for (int nb = 0; nb < 2; nb++) {
            const u32 o = hoff + sw128((u32)((wn + nb * 16 + b_row) * 128 + (kp + b_kb) * 2));
            ldsm4(sBh + o, Bh[nb]);
            ldsm4(sBl + o, Bl[nb]);
        }
        #pragma unroll
        for (int mi = 0; mi < 2; mi++)
            #pragma unroll
            for (int ni = 0; ni < 4; ni++) {
                const u32* bh = Bh[ni >> 1] + (ni & 1) * 2;
                const u32* bl = Bl[ni >> 1] + (ni & 1) * 2;
                mma_bf16(accL[mi][ni], Ah[mi], bh);
                mma_bf16(accL[mi][ni], Ah[mi], bl);
                mma_bf16(accL[mi][ni], Al[mi], bh);
            }
    }

    #pragma unroll
    for (int mi = 0; mi < 2; mi++) {
        const int r0 = wm + mi * 16 + (lane >> 2);
        #pragma unroll
        for (int ni = 0; ni < 4; ni++) {
            const int c = wn + ni * 8 + (lane & 3) * 2;
            const float b0 = __ldg(bo + c), b1 = __ldg(bo + c + 1);
            const size_t ro0 = (size_t)(rowbase + r0) * C + c;
            const size_t ro1 = (size_t)(rowbase + r0 + 8) * C + c;
            const float2 gg0 = *(const float2*)(g_go + ro0);
            const float2 gg1 = *(const float2*)(g_go + ro1);
            *(float2*)(out + ro0)
                = make_float2(gg0.x * (accL[mi][ni][0] + b0), gg0.y * (accL[mi][ni][1] + b1));
            *(float2*)(out + ro1)
                = make_float2(gg1.x * (accL[mi][ni][2] + b0), gg1.y * (accL[mi][ni][3] + b1));
        }
    }
}

// ============================================================================
extern "C" void kernel_launch(void* const* d_in, const int* in_sizes, int n_in,
                              void* d_out, int out_size)
{
    const float*         z    = (const float*)d_in[0];
    const unsigned char* mask = (const unsigned char*)d_in[1];
    const float* gin = (const float*)d_in[2],  *bin = (const float*)d_in[3];
    const float* Wa  = (const float*)d_in[4],  *ba  = (const float*)d_in[5];
    const float* Wga = (const float*)d_in[6],  *bga = (const float*)d_in[7];
    const float* Wb  = (const float*)d_in[8],  *bb  = (const float*)d_in[9];
    const float* Wgb = (const float*)d_in[10], *bgb = (const float*)d_in[11];
    const float* g_o = (const float*)d_in[12], *b_o = (const float*)d_in[13];
    const float* Wgo = (const float*)d_in[14], *bgo = (const float*)d_in[15];
    const float* Wo  = (const float*)d_in[16], *bo  = (const float*)d_in[17];
    float* out = (float*)d_out;

    static int attr_set = 0;
    if (!attr_set) {
        cudaFuncSetAttribute(kB, cudaFuncAttributeMaxDynamicSharedMemorySize, KB_SMEM);
        cudaFuncSetAttribute(kProjA, cudaFuncAttributeMaxDynamicSharedMemorySize, PJ_SMEM);
        cudaFuncSetAttribute(kOut, cudaFuncAttributeMaxDynamicSharedMemorySize, KO_SMEM);
        attr_set = 1;
    }

    kW<<<6, 256>>>(Wa, Wga, Wb, Wgb, Wgo, Wo);
    kProjA<<<2048, 512, PJ_SMEM>>>(z, mask, gin, bin, ba, bga, bb, bgb, bgo);
    kB<<<dim3(16, C), 256, KB_SMEM>>>();
    kOut<<<2048, 512, KO_SMEM>>>(g_o, b_o, bo, out);
}